// round 1
// baseline (speedup 1.0000x reference)
#include <cuda_runtime.h>
#include <cuda_bf16.h>
#include <math.h>

// Problem constants
#define BB   4
#define TT   4096
#define DIN  1024
#define HH   16
#define DD   64
#define MM   (BB*TT)        // 16384
#define NN   (HH*DD*2)      // 2048
#define CC   64             // chunks per (b,h)
#define LL   (TT/CC)        // 64 steps per chunk

// Scratch (device globals; no allocation allowed)
__device__ float g_k[MM * (HH*DD)];       // 64 MiB  packed k [m, h*64+d]
__device__ float g_v[MM * (HH*DD)];       // 64 MiB  packed v [m, h*64+d]
__device__ float g_s[MM * HH];            // 1 MiB   s [m, h]
__device__ float g_cm[BB*HH*CC];
__device__ float g_cu[BB*HH*CC];
__device__ float g_cw[BB*HH*CC*DD];
__device__ float g_hv[(size_t)BB*HH*TT*DD]; // 64 MiB h-per-head [bh, t, d]

// ---------------------------------------------------------------------------
// GEMM: Y = relu(X @ W), X[M,K] K=1024, W[K,N] N=2048, de-interleaved epilogue
// BM=128 BN=128 BK=8 TM=8 TN=8, 256 threads
// ---------------------------------------------------------------------------
__global__ __launch_bounds__(256) void gemm_kv(const float* __restrict__ X,
                                               const float* __restrict__ W) {
    __shared__ float As[8][128];
    __shared__ float Bs[8][128];

    const int tid  = threadIdx.x;
    const int brow = blockIdx.y * 128;
    const int bcol = blockIdx.x * 128;

    const int aRow = tid >> 1;          // 0..127
    const int aCol = (tid & 1) * 4;     // 0 / 4
    const int bRow = tid >> 5;          // 0..7
    const int bCol = (tid & 31) * 4;    // 0..124

    const int tx = tid & 15;            // 16 col groups
    const int ty = tid >> 4;            // 16 row groups

    float acc[8][8];
#pragma unroll
    for (int i = 0; i < 8; i++)
#pragma unroll
        for (int j = 0; j < 8; j++) acc[i][j] = 0.f;

    for (int k0 = 0; k0 < DIN; k0 += 8) {
        float4 a = *(const float4*)&X[(size_t)(brow + aRow) * DIN + k0 + aCol];
        As[aCol + 0][aRow] = a.x;
        As[aCol + 1][aRow] = a.y;
        As[aCol + 2][aRow] = a.z;
        As[aCol + 3][aRow] = a.w;
        float4 b = *(const float4*)&W[(size_t)(k0 + bRow) * NN + bcol + bCol];
        *(float4*)&Bs[bRow][bCol] = b;
        __syncthreads();

#pragma unroll
        for (int kk = 0; kk < 8; kk++) {
            float ar[8], br[8];
#pragma unroll
            for (int i = 0; i < 8; i++) ar[i] = As[kk][ty * 8 + i];
#pragma unroll
            for (int j = 0; j < 8; j++) br[j] = Bs[kk][tx * 8 + j];
#pragma unroll
            for (int i = 0; i < 8; i++)
#pragma unroll
                for (int j = 0; j < 8; j++) acc[i][j] += ar[i] * br[j];
        }
        __syncthreads();
    }

    // Epilogue: n = bcol + tx*8 + j. Even n -> k, odd n -> v, d0 = n/2.
    const int d0 = (bcol >> 1) + tx * 4;   // index into [h*64+d] space, mult of 4
#pragma unroll
    for (int i = 0; i < 8; i++) {
        const int m = brow + ty * 8 + i;
        float4 k4, v4;
        k4.x = fmaxf(acc[i][0], 0.f); v4.x = fmaxf(acc[i][1], 0.f);
        k4.y = fmaxf(acc[i][2], 0.f); v4.y = fmaxf(acc[i][3], 0.f);
        k4.z = fmaxf(acc[i][4], 0.f); v4.z = fmaxf(acc[i][5], 0.f);
        k4.w = fmaxf(acc[i][6], 0.f); v4.w = fmaxf(acc[i][7], 0.f);
        *(float4*)&g_k[(size_t)m * (HH*DD) + d0] = k4;
        *(float4*)&g_v[(size_t)m * (HH*DD) + d0] = v4;
    }
}

// ---------------------------------------------------------------------------
// s[m,h] = sum_d q[h,d] * k[m,h*64+d]. One block per m, 128 threads.
// ---------------------------------------------------------------------------
__global__ __launch_bounds__(128) void s_kernel(const float* __restrict__ q) {
    const int m   = blockIdx.x;
    const int tid = threadIdx.x;
    const int h   = tid >> 3;    // 0..15
    const int sub = tid & 7;     // 0..7

    float p = 0.f;
#pragma unroll
    for (int dd = 0; dd < 8; dd++) {
        const int d = sub * 8 + dd;
        p += q[h * DD + d] * g_k[(size_t)m * (HH*DD) + h * DD + d];
    }

    __shared__ float red[128];
    red[tid] = p;
    __syncthreads();
    if (sub < 4) red[tid] += red[tid + 4];
    __syncthreads();
    if (sub < 2) red[tid] += red[tid + 2];
    __syncthreads();
    if (sub == 0) g_s[m * HH + h] = red[tid] + red[tid + 1];
}

// ---------------------------------------------------------------------------
// Scan phase A: per-chunk local aggregates. grid = B*H*C blocks, 64 threads.
// ---------------------------------------------------------------------------
__global__ __launch_bounds__(64) void scanA() {
    const int idx = blockIdx.x;          // bh*CC + c
    const int bh  = idx / CC;
    const int c   = idx % CC;
    const int b   = bh >> 4;
    const int h   = bh & 15;
    const int d   = threadIdx.x;

    float m = -1e30f, u = 0.f, w = 0.f;
    const int t0 = c * LL;
#pragma unroll 4
    for (int tt = 0; tt < LL; tt++) {
        const int mrow = b * TT + t0 + tt;
        const float s = g_s[mrow * HH + h];
        const float v = g_v[(size_t)mrow * (HH*DD) + h * DD + d];
        const float nm = fmaxf(m, s);
        const float a = __expf(m - nm);
        const float e = __expf(s - nm);
        u = u * a + e;
        w = w * a + e * v;
        m = nm;
    }
    if (d == 0) { g_cm[idx] = m; g_cu[idx] = u; }
    g_cw[idx * DD + d] = w;
}

// ---------------------------------------------------------------------------
// Scan phase B: sequential exclusive scan over chunk aggregates (in place).
// grid = B*H blocks, 64 threads.
// ---------------------------------------------------------------------------
__global__ __launch_bounds__(64) void scanB() {
    const int bh = blockIdx.x;
    const int d  = threadIdx.x;

    float mC = -1e30f, uC = 0.f, wC = 0.f;
    for (int c = 0; c < CC; c++) {
        const int idx = bh * CC + c;
        const float ma = g_cm[idx];
        const float ua = g_cu[idx];
        const float wa = g_cw[idx * DD + d];
        __syncthreads();                       // all reads done before overwrite
        if (d == 0) { g_cm[idx] = mC; g_cu[idx] = uC; }
        g_cw[idx * DD + d] = wC;
        const float nm = fmaxf(mC, ma);
        const float ea = __expf(mC - nm);
        const float eb = __expf(ma - nm);
        uC = uC * ea + ua * eb;
        wC = wC * ea + wa * eb;
        mC = nm;
    }
}

// ---------------------------------------------------------------------------
// Scan phase C: replay chunk with exclusive-prefix carry, emit w/u per t.
// grid = B*H*C blocks, 64 threads.
// ---------------------------------------------------------------------------
__global__ __launch_bounds__(64) void scanC() {
    const int idx = blockIdx.x;
    const int bh  = idx / CC;
    const int c   = idx % CC;
    const int b   = bh >> 4;
    const int h   = bh & 15;
    const int d   = threadIdx.x;

    float m = g_cm[idx];
    float u = g_cu[idx];
    float w = g_cw[idx * DD + d];
    const int t0 = c * LL;
#pragma unroll 4
    for (int tt = 0; tt < LL; tt++) {
        const int t = t0 + tt;
        const int mrow = b * TT + t;
        const float s = g_s[mrow * HH + h];
        const float v = g_v[(size_t)mrow * (HH*DD) + h * DD + d];
        const float nm = fmaxf(m, s);
        const float a = __expf(m - nm);
        const float e = __expf(s - nm);
        u = u * a + e;
        w = w * a + e * v;
        m = nm;
        g_hv[((size_t)bh * TT + t) * DD + d] = w / u;
    }
}

// ---------------------------------------------------------------------------
// Reduce over heads: out[b,t,d] = sum_h hv[b,h,t,d]
// ---------------------------------------------------------------------------
__global__ __launch_bounds__(256) void reduceH(float* __restrict__ out) {
    const int idx = blockIdx.x * 256 + threadIdx.x;   // < B*T*D
    const int b = idx / (TT * DD);
    const int r = idx % (TT * DD);
    float acc = 0.f;
#pragma unroll
    for (int h = 0; h < HH; h++)
        acc += g_hv[((size_t)(b * HH + h) * TT) * DD + r];
    out[idx] = acc;
}

extern "C" void kernel_launch(void* const* d_in, const int* in_sizes, int n_in,
                              void* d_out, int out_size) {
    const float* X = (const float*)d_in[0];   // [B,T,DIN]
    const float* W = (const float*)d_in[1];   // [DIN,H,D,2] == [1024,2048]
    const float* q = (const float*)d_in[2];   // [H,D]
    float* out = (float*)d_out;               // [B,T,D]

    gemm_kv<<<dim3(NN / 128, MM / 128), 256>>>(X, W);
    s_kernel<<<MM, 128>>>(q);
    scanA<<<BB * HH * CC, 64>>>();
    scanB<<<BB * HH, 64>>>();
    scanC<<<BB * HH * CC, 64>>>();
    reduceH<<<(BB * TT * DD) / 256, 256>>>(out);
}

// round 6
// speedup vs baseline: 4.7181x; 4.7181x over previous
#include <cuda_runtime.h>
#include <cuda_fp16.h>
#include <math.h>
#include <stdint.h>

// Problem constants
#define BB   4
#define TT   4096
#define DIN  1024
#define HH   16
#define DD   64
#define MM   (BB*TT)        // 16384
#define NN   (HH*DD*2)      // 2048
#define CC   64             // scan chunks per (b,h)
#define LL   (TT/CC)        // 64

// GEMM tiling
#define GBM 128
#define GBN 128
#define GBK 64
#define STAGES 4
#define KITERS (DIN/GBK)    // 16
#define STAGE_BYTES 32768u  // 16KB A + 16KB B

// ---------------------------------------------------------------------------
// Scratch (device globals; no allocation allowed)
// ---------------------------------------------------------------------------
__device__ __half g_Xh[(size_t)MM * DIN];      // 32 MiB
__device__ __half g_Wt[(size_t)NN * DIN];      // 4 MiB  (transposed W: [n][k])
__device__ float  g_v[(size_t)MM * (HH*DD)];   // 64 MiB packed relu(v) [m][h*64+d]
__device__ float  g_s[MM * HH];                // 1 MiB
__device__ float  g_cm[BB*HH*CC];
__device__ float  g_cu[BB*HH*CC];
__device__ float  g_cw[BB*HH*CC*DD];

// ---------------------------------------------------------------------------
// asm helpers
// ---------------------------------------------------------------------------
__device__ __forceinline__ uint32_t smem_u32(const void* p) {
    uint32_t a;
    asm("{ .reg .u64 t; cvta.to.shared.u64 t, %1; cvt.u32.u64 %0, t; }" : "=r"(a) : "l"(p));
    return a;
}
__device__ __forceinline__ void cp16(uint32_t dst, const void* src) {
    asm volatile("cp.async.cg.shared.global [%0], [%1], 16;" :: "r"(dst), "l"(src));
}
__device__ __forceinline__ void ldm4(uint32_t* r, uint32_t addr) {
    asm volatile("ldmatrix.sync.aligned.m8n8.x4.shared.b16 {%0,%1,%2,%3}, [%4];"
                 : "=r"(r[0]), "=r"(r[1]), "=r"(r[2]), "=r"(r[3]) : "r"(addr));
}
__device__ __forceinline__ void mma16816(float* c, const uint32_t* a, const uint32_t* b) {
    asm volatile("mma.sync.aligned.m16n8k16.row.col.f32.f16.f16.f32 "
                 "{%0,%1,%2,%3}, {%4,%5,%6,%7}, {%8,%9}, {%0,%1,%2,%3};"
                 : "+f"(c[0]), "+f"(c[1]), "+f"(c[2]), "+f"(c[3])
                 : "r"(a[0]), "r"(a[1]), "r"(a[2]), "r"(a[3]), "r"(b[0]), "r"(b[1]));
}

// ---------------------------------------------------------------------------
// Prep: X fp32 -> fp16 (8 floats / thread)
// ---------------------------------------------------------------------------
__global__ __launch_bounds__(256) void convX(const float* __restrict__ X) {
    size_t i = (size_t)blockIdx.x * 256 + threadIdx.x;   // < 2M
    const float4* src = (const float4*)X + i * 2;
    float4 x0 = src[0], x1 = src[1];
    __half2 h0 = __floats2half2_rn(x0.x, x0.y);
    __half2 h1 = __floats2half2_rn(x0.z, x0.w);
    __half2 h2 = __floats2half2_rn(x1.x, x1.y);
    __half2 h3 = __floats2half2_rn(x1.z, x1.w);
    uint4 o;
    o.x = *(uint32_t*)&h0; o.y = *(uint32_t*)&h1;
    o.z = *(uint32_t*)&h2; o.w = *(uint32_t*)&h3;
    ((uint4*)g_Xh)[i] = o;
}

// Prep: W [K=1024][N=2048] fp32 -> g_Wt fp16 [N][K]
__global__ void convW(const float* __restrict__ W) {
    __shared__ float tile[32][33];
    const int n0 = blockIdx.x * 32, k0 = blockIdx.y * 32;
    const int tx = threadIdx.x, ty = threadIdx.y;        // 32 x 8
    for (int r = ty; r < 32; r += 8)
        tile[r][tx] = W[(size_t)(k0 + r) * NN + n0 + tx];
    __syncthreads();
    for (int r = ty; r < 32; r += 8)
        g_Wt[(size_t)(n0 + r) * DIN + k0 + tx] = __float2half(tile[tx][r]);
}

// ---------------------------------------------------------------------------
// GEMM via mma.sync: kv = relu(X @ W), fused de-interleave + s = q . relu(k)
// CTA 128x128x64, 256 threads (8 warps, 2x4), 4-stage cp.async.
// blockIdx.x = head h (N-tile covers exactly one head), blockIdx.y = M-tile.
// ---------------------------------------------------------------------------
__device__ __forceinline__ void issue_stage(uint32_t sb, int stage, int kc,
                                            int bm, int bn, int tid) {
    const uint32_t so = sb + (uint32_t)stage * STAGE_BYTES;
    const int k0 = kc * GBK;
#pragma unroll
    for (int i = 0; i < 4; i++) {
        int idx = tid + i * 256;
        int row = idx >> 3, ch = idx & 7;
        cp16(so + row * 128 + ((uint32_t)(ch ^ (row & 7)) << 4),
             g_Xh + (size_t)(bm + row) * DIN + k0 + ch * 8);
    }
#pragma unroll
    for (int i = 0; i < 4; i++) {
        int idx = tid + i * 256;
        int row = idx >> 3, ch = idx & 7;
        cp16(so + 16384u + row * 128 + ((uint32_t)(ch ^ (row & 7)) << 4),
             g_Wt + (size_t)(bn + row) * DIN + k0 + ch * 8);
    }
}

__global__ __launch_bounds__(256) void gemm_mma(const float* __restrict__ qk) {
    extern __shared__ char sm[];
    __shared__ float sred[128][4];
    const uint32_t sb = smem_u32(sm);
    const int tid = threadIdx.x;
    const int wid = tid >> 5, lane = tid & 31;
    const int wm = wid >> 2, wn = wid & 3;
    const int h  = blockIdx.x;
    const int bn = h << 7;
    const int bm = blockIdx.y * GBM;

    float acc[4][4][4];
#pragma unroll
    for (int a = 0; a < 4; a++)
#pragma unroll
        for (int b = 0; b < 4; b++)
#pragma unroll
            for (int c = 0; c < 4; c++) acc[a][b][c] = 0.f;

    // ldmatrix per-thread geometry
    const int arow = lane & 15;
    const int asel = lane >> 4;                    // A chunk select
    const int asw  = arow & 7;
    const int brow = (lane & 7) | (((lane >> 4) & 1) << 3);
    const int bsel = (lane >> 3) & 1;              // B chunk select
    const int bsw  = brow & 7;
    uint32_t a_off[4], b_off[2];
#pragma unroll
    for (int mt = 0; mt < 4; mt++) a_off[mt] = (uint32_t)(wm * 64 + mt * 16 + arow) * 128;
#pragma unroll
    for (int bt = 0; bt < 2; bt++) b_off[bt] = 16384u + (uint32_t)(wn * 32 + bt * 16 + brow) * 128;

    // pipeline prologue
    for (int s = 0; s < STAGES - 1; s++) {
        issue_stage(sb, s, s, bm, bn, tid);
        asm volatile("cp.async.commit_group;" ::: "memory");
    }

    for (int kc = 0; kc < KITERS; kc++) {
        asm volatile("cp.async.wait_group 2;" ::: "memory");
        __syncthreads();

        if (kc + STAGES - 1 < KITERS)
            issue_stage(sb, (kc + STAGES - 1) & (STAGES - 1), kc + STAGES - 1, bm, bn, tid);
        asm volatile("cp.async.commit_group;" ::: "memory");

        const uint32_t so = sb + (uint32_t)(kc & (STAGES - 1)) * STAGE_BYTES;
#pragma unroll
        for (int ks = 0; ks < 4; ks++) {
            uint32_t af[4][4], bf[2][4];
#pragma unroll
            for (int mt = 0; mt < 4; mt++)
                ldm4(af[mt], so + a_off[mt] + ((uint32_t)(((ks << 1) | asel) ^ asw) << 4));
#pragma unroll
            for (int bt = 0; bt < 2; bt++)
                ldm4(bf[bt], so + b_off[bt] + ((uint32_t)(((ks << 1) | bsel) ^ bsw) << 4));
#pragma unroll
            for (int mt = 0; mt < 4; mt++) {
                mma16816(acc[mt][0], af[mt], &bf[0][0]);
                mma16816(acc[mt][1], af[mt], &bf[0][2]);
                mma16816(acc[mt][2], af[mt], &bf[1][0]);
                mma16816(acc[mt][3], af[mt], &bf[1][2]);
            }
        }
    }

    // ------------- fused epilogue -------------
    // c0,c1 = (k,v) at row gq; c2,c3 = (k,v) at row gq+8; d = wn*16+nt*4+qd
    const int gq = lane >> 2, qd = lane & 3;
    float qv[4];
#pragma unroll
    for (int nt = 0; nt < 4; nt++)
        qv[nt] = __ldg(&qk[h * DD + wn * 16 + nt * 4 + qd]);

#pragma unroll
    for (int mt = 0; mt < 4; mt++) {
        const int ml0 = wm * 64 + mt * 16 + gq;
        const int m0  = bm + ml0;
        float s0 = 0.f, s1 = 0.f;
#pragma unroll
        for (int nt = 0; nt < 4; nt++) {
            const int dl = wn * 16 + nt * 4 + qd;
            float k0 = fmaxf(acc[mt][nt][0], 0.f), v0 = fmaxf(acc[mt][nt][1], 0.f);
            float k1 = fmaxf(acc[mt][nt][2], 0.f), v1 = fmaxf(acc[mt][nt][3], 0.f);
            s0 += qv[nt] * k0;
            s1 += qv[nt] * k1;
            g_v[(size_t)m0 * (HH*DD) + h * DD + dl]       = v0;
            g_v[(size_t)(m0 + 8) * (HH*DD) + h * DD + dl] = v1;
        }
        s0 += __shfl_xor_sync(0xFFFFFFFF, s0, 1);
        s0 += __shfl_xor_sync(0xFFFFFFFF, s0, 2);
        s1 += __shfl_xor_sync(0xFFFFFFFF, s1, 1);
        s1 += __shfl_xor_sync(0xFFFFFFFF, s1, 2);
        if (qd == 0) {
            sred[ml0][wn]     = s0;
            sred[ml0 + 8][wn] = s1;
        }
    }
    __syncthreads();
    if (tid < 128) {
        float s = sred[tid][0] + sred[tid][1] + sred[tid][2] + sred[tid][3];
        g_s[(bm + tid) * HH + h] = s;
    }
}

// ---------------------------------------------------------------------------
// Scan phase A: per-chunk local aggregates. grid = B*H*C, 64 threads.
// ---------------------------------------------------------------------------
__global__ __launch_bounds__(64) void scanA() {
    const int idx = blockIdx.x;
    const int bh  = idx / CC;
    const int c   = idx % CC;
    const int b   = bh >> 4;
    const int h   = bh & 15;
    const int d   = threadIdx.x;

    float m = -1e30f, u = 0.f, w = 0.f;
    const int t0 = c * LL;
#pragma unroll 4
    for (int tt = 0; tt < LL; tt++) {
        const int mrow = b * TT + t0 + tt;
        const float s = g_s[mrow * HH + h];
        const float v = g_v[(size_t)mrow * (HH*DD) + h * DD + d];
        const float nm = fmaxf(m, s);
        const float a = __expf(m - nm);
        const float e = __expf(s - nm);
        u = u * a + e;
        w = w * a + e * v;
        m = nm;
    }
    if (d == 0) { g_cm[idx] = m; g_cu[idx] = u; }
    g_cw[idx * DD + d] = w;
}

// ---------------------------------------------------------------------------
// Scan phase B: exclusive scan over chunk aggregates, smem-staged.
// grid = B*H, 64 threads.
// ---------------------------------------------------------------------------
__global__ __launch_bounds__(64) void scanB() {
    __shared__ float scm[CC], scu[CC], scw[CC * DD];
    const int bh = blockIdx.x;
    const int d  = threadIdx.x;

    for (int c = 0; c < CC; c++)
        scw[c * DD + d] = g_cw[(bh * CC + c) * DD + d];
    scm[d] = g_cm[bh * CC + d];
    scu[d] = g_cu[bh * CC + d];
    __syncthreads();

    float mC = -1e30f, uC = 0.f, wC = 0.f;
    for (int c = 0; c < CC; c++) {
        const int idx = bh * CC + c;
        const float ma = scm[c];
        const float ua = scu[c];
        const float wa = scw[c * DD + d];
        g_cw[idx * DD + d] = wC;                    // exclusive prefix out
        if (d == 0) { g_cm[idx] = mC; g_cu[idx] = uC; }
        const float nm = fmaxf(mC, ma);
        const float ea = __expf(mC - nm);
        const float eb = __expf(ma - nm);
        uC = uC * ea + ua * eb;
        wC = wC * ea + wa * eb;
        mC = nm;
    }
}

// ---------------------------------------------------------------------------
// Scan phase C fused with head-reduction: out[b,t,d] = sum_h w/u.
// grid = B*C blocks, 256 threads (4 h-groups x 64 d).
// ---------------------------------------------------------------------------
__global__ __launch_bounds__(256) void scanCR(float* __restrict__ out) {
    __shared__ float accS[LL][DD];                  // 16 KB
    const int b  = blockIdx.x / CC;
    const int c  = blockIdx.x % CC;
    const int tid = threadIdx.x;
    const int hs = tid >> 6;                        // 0..3
    const int d  = tid & 63;

    for (int i = tid; i < LL * DD; i += 256) ((float*)accS)[i] = 0.f;
    __syncthreads();

    const int t0 = c * LL;
#pragma unroll
    for (int hi = 0; hi < 4; hi++) {
        const int h   = hs * 4 + hi;
        const int idx = (b * HH + h) * CC + c;
        float m = g_cm[idx];
        float u = g_cu[idx];
        float w = g_cw[idx * DD + d];
#pragma unroll 4
        for (int tt = 0; tt < LL; tt++) {
            const int mrow = b * TT + t0 + tt;
            const float s = g_s[mrow * HH + h];
            const float v = g_v[(size_t)mrow * (HH*DD) + h * DD + d];
            const float nm = fmaxf(m, s);
            const float a = __expf(m - nm);
            const float e = __expf(s - nm);
            u = u * a + e;
            w = w * a + e * v;
            m = nm;
            atomicAdd(&accS[tt][d], w / u);
        }
    }
    __syncthreads();
    for (int i = tid; i < LL * DD; i += 256) {
        const int tt = i >> 6, dd = i & 63;
        out[((size_t)b * TT + t0 + tt) * DD + dd] = accS[tt][dd];
    }
}

extern "C" void kernel_launch(void* const* d_in, const int* in_sizes, int n_in,
                              void* d_out, int out_size) {
    const float* X = (const float*)d_in[0];   // [B,T,DIN]
    const float* W = (const float*)d_in[1];   // [DIN, 2048]
    const float* q = (const float*)d_in[2];   // [H,D]
    float* out = (float*)d_out;               // [B,T,D]

    const int gemm_smem = STAGES * (int)STAGE_BYTES;   // 131072
    cudaFuncSetAttribute(gemm_mma, cudaFuncAttributeMaxDynamicSharedMemorySize,
                         gemm_smem);

    convX<<<(MM * DIN) / (256 * 8), 256>>>(X);
    convW<<<dim3(NN / 32, DIN / 32), dim3(32, 8)>>>(W);
    gemm_mma<<<dim3(HH, MM / GBM), 256, gemm_smem>>>(q);
    scanA<<<BB * HH * CC, 64>>>();
    scanB<<<BB * HH, 64>>>();
    scanCR<<<BB * CC, 256>>>(out);
}

// round 7
// speedup vs baseline: 5.7881x; 1.2268x over previous
#include <cuda_runtime.h>
#include <cuda_fp16.h>
#include <math.h>
#include <stdint.h>

// Problem constants
#define BB   4
#define TT   4096
#define DIN  1024
#define HH   16
#define DD   64
#define MM   (BB*TT)        // 16384
#define NN   (HH*DD*2)      // 2048
#define CC   64             // scan chunks per (b,h)
#define LL   (TT/CC)        // 64

// GEMM tiling: 256x128x64, 512 threads (16 warps, 4x4, warp tile 64x32)
#define GBM 256
#define GBN 128
#define GBK 64
#define STAGES 4
#define KITERS (DIN/GBK)    // 16
#define STAGE_BYTES 49152u  // 32KB A + 16KB B

// ---------------------------------------------------------------------------
// Scratch (device globals; no allocation allowed)
// ---------------------------------------------------------------------------
__device__ __half g_Xh[(size_t)MM * DIN];      // 32 MiB
__device__ __half g_Wt[(size_t)NN * DIN];      // 4 MiB  (transposed W: [n][k])
__device__ float  g_v[(size_t)MM * (HH*DD)];   // 64 MiB packed relu(v) [m][h*64+d]
__device__ float  g_s[MM * HH];                // 1 MiB
__device__ float  g_cm[BB*HH*CC];
__device__ float  g_cu[BB*HH*CC];
__device__ float  g_cw[BB*HH*CC*DD];

// ---------------------------------------------------------------------------
// asm helpers
// ---------------------------------------------------------------------------
__device__ __forceinline__ uint32_t smem_u32(const void* p) {
    uint32_t a;
    asm("{ .reg .u64 t; cvta.to.shared.u64 t, %1; cvt.u32.u64 %0, t; }" : "=r"(a) : "l"(p));
    return a;
}
__device__ __forceinline__ void cp16(uint32_t dst, const void* src) {
    asm volatile("cp.async.cg.shared.global [%0], [%1], 16;" :: "r"(dst), "l"(src));
}
__device__ __forceinline__ void ldm4(uint32_t* r, uint32_t addr) {
    asm volatile("ldmatrix.sync.aligned.m8n8.x4.shared.b16 {%0,%1,%2,%3}, [%4];"
                 : "=r"(r[0]), "=r"(r[1]), "=r"(r[2]), "=r"(r[3]) : "r"(addr));
}
__device__ __forceinline__ void mma16816(float* c, const uint32_t* a, const uint32_t* b) {
    asm volatile("mma.sync.aligned.m16n8k16.row.col.f32.f16.f16.f32 "
                 "{%0,%1,%2,%3}, {%4,%5,%6,%7}, {%8,%9}, {%0,%1,%2,%3};"
                 : "+f"(c[0]), "+f"(c[1]), "+f"(c[2]), "+f"(c[3])
                 : "r"(a[0]), "r"(a[1]), "r"(a[2]), "r"(a[3]), "r"(b[0]), "r"(b[1]));
}

// ---------------------------------------------------------------------------
// Prep: X fp32 -> fp16 (8 floats / thread)
// ---------------------------------------------------------------------------
__global__ __launch_bounds__(256) void convX(const float* __restrict__ X) {
    size_t i = (size_t)blockIdx.x * 256 + threadIdx.x;   // < 2M
    const float4* src = (const float4*)X + i * 2;
    float4 x0 = src[0], x1 = src[1];
    __half2 h0 = __floats2half2_rn(x0.x, x0.y);
    __half2 h1 = __floats2half2_rn(x0.z, x0.w);
    __half2 h2 = __floats2half2_rn(x1.x, x1.y);
    __half2 h3 = __floats2half2_rn(x1.z, x1.w);
    uint4 o;
    o.x = *(uint32_t*)&h0; o.y = *(uint32_t*)&h1;
    o.z = *(uint32_t*)&h2; o.w = *(uint32_t*)&h3;
    ((uint4*)g_Xh)[i] = o;
}

// Prep: W [K=1024][N=2048] fp32 -> g_Wt fp16 [N][K]
__global__ void convW(const float* __restrict__ W) {
    __shared__ float tile[32][33];
    const int n0 = blockIdx.x * 32, k0 = blockIdx.y * 32;
    const int tx = threadIdx.x, ty = threadIdx.y;        // 32 x 8
    for (int r = ty; r < 32; r += 8)
        tile[r][tx] = W[(size_t)(k0 + r) * NN + n0 + tx];
    __syncthreads();
    for (int r = ty; r < 32; r += 8)
        g_Wt[(size_t)(n0 + r) * DIN + k0 + tx] = __float2half(tile[tx][r]);
}

// ---------------------------------------------------------------------------
// GEMM via mma.sync: kv = relu(X @ W); fused: de-interleave v, s = q.relu(k),
// AND per-chunk scan aggregates (m, u, w[64]) -> g_cm/g_cu/g_cw (kills scanA).
// CTA 256x128x64, 512 threads, 4-stage cp.async.
// blockIdx.x = head h, blockIdx.y = M-tile (256 rows = 4 scan chunks).
// ---------------------------------------------------------------------------
__device__ __forceinline__ void issue_stage(uint32_t sb, int stage, int kc,
                                            int bm, int bn, int tid) {
    const uint32_t so = sb + (uint32_t)stage * STAGE_BYTES;
    const int k0 = kc * GBK;
#pragma unroll
    for (int i = 0; i < 4; i++) {                        // A: 256 rows x 128B
        int idx = tid + i * 512;
        int row = idx >> 3, ch = idx & 7;
        cp16(so + row * 128 + ((uint32_t)(ch ^ (row & 7)) << 4),
             g_Xh + (size_t)(bm + row) * DIN + k0 + ch * 8);
    }
#pragma unroll
    for (int i = 0; i < 2; i++) {                        // B: 128 rows x 128B
        int idx = tid + i * 512;
        int row = idx >> 3, ch = idx & 7;
        cp16(so + 32768u + row * 128 + ((uint32_t)(ch ^ (row & 7)) << 4),
             g_Wt + (size_t)(bn + row) * DIN + k0 + ch * 8);
    }
}

__global__ __launch_bounds__(512) void gemm_mma(const float* __restrict__ qk) {
    extern __shared__ char sm[];
    __shared__ float sred[256][4];
    __shared__ float ssm[256];
    const uint32_t sb = smem_u32(sm);
    const int tid = threadIdx.x;
    const int wid = tid >> 5, lane = tid & 31;
    const int wm = wid >> 2, wn = wid & 3;               // 4 x 4 warps
    const int h  = blockIdx.x;
    const int bn = h << 7;
    const int bm = blockIdx.y * GBM;

    float acc[4][4][4];
#pragma unroll
    for (int a = 0; a < 4; a++)
#pragma unroll
        for (int b = 0; b < 4; b++)
#pragma unroll
            for (int c = 0; c < 4; c++) acc[a][b][c] = 0.f;

    // ldmatrix per-thread geometry
    const int arow = lane & 15;
    const int asel = lane >> 4;
    const int asw  = arow & 7;
    const int brow = (lane & 7) | (((lane >> 4) & 1) << 3);
    const int bsel = (lane >> 3) & 1;
    const int bsw  = brow & 7;
    uint32_t a_off[4], b_off[2];
#pragma unroll
    for (int mt = 0; mt < 4; mt++) a_off[mt] = (uint32_t)(wm * 64 + mt * 16 + arow) * 128;
#pragma unroll
    for (int bt = 0; bt < 2; bt++) b_off[bt] = 32768u + (uint32_t)(wn * 32 + bt * 16 + brow) * 128;

    // pipeline prologue
    for (int s = 0; s < STAGES - 1; s++) {
        issue_stage(sb, s, s, bm, bn, tid);
        asm volatile("cp.async.commit_group;" ::: "memory");
    }

    for (int kc = 0; kc < KITERS; kc++) {
        asm volatile("cp.async.wait_group 2;" ::: "memory");
        __syncthreads();

        if (kc + STAGES - 1 < KITERS)
            issue_stage(sb, (kc + STAGES - 1) & (STAGES - 1), kc + STAGES - 1, bm, bn, tid);
        asm volatile("cp.async.commit_group;" ::: "memory");

        const uint32_t so = sb + (uint32_t)(kc & (STAGES - 1)) * STAGE_BYTES;
#pragma unroll
        for (int ks = 0; ks < 4; ks++) {
            uint32_t af[4][4], bf[2][4];
#pragma unroll
            for (int mt = 0; mt < 4; mt++)
                ldm4(af[mt], so + a_off[mt] + ((uint32_t)(((ks << 1) | asel) ^ asw) << 4));
#pragma unroll
            for (int bt = 0; bt < 2; bt++)
                ldm4(bf[bt], so + b_off[bt] + ((uint32_t)(((ks << 1) | bsel) ^ bsw) << 4));
#pragma unroll
            for (int mt = 0; mt < 4; mt++) {
                mma16816(acc[mt][0], af[mt], &bf[0][0]);
                mma16816(acc[mt][1], af[mt], &bf[0][2]);
                mma16816(acc[mt][2], af[mt], &bf[1][0]);
                mma16816(acc[mt][3], af[mt], &bf[1][2]);
            }
        }
    }

    // ------------- fused epilogue -------------
    // c0,c1 = (k,v) at row gq; c2,c3 = (k,v) at row gq+8; d = wn*16+nt*4+qd
    const int gq = lane >> 2, qd = lane & 3;
    float qv[4];
#pragma unroll
    for (int nt = 0; nt < 4; nt++)
        qv[nt] = __ldg(&qk[h * DD + wn * 16 + nt * 4 + qd]);

#pragma unroll
    for (int mt = 0; mt < 4; mt++) {
        const int ml0 = wm * 64 + mt * 16 + gq;
        const int m0  = bm + ml0;
        float s0 = 0.f, s1 = 0.f;
#pragma unroll
        for (int nt = 0; nt < 4; nt++) {
            const int dl = wn * 16 + nt * 4 + qd;
            float k0 = fmaxf(acc[mt][nt][0], 0.f), v0 = fmaxf(acc[mt][nt][1], 0.f);
            float k1 = fmaxf(acc[mt][nt][2], 0.f), v1 = fmaxf(acc[mt][nt][3], 0.f);
            s0 += qv[nt] * k0;
            s1 += qv[nt] * k1;
            acc[mt][nt][1] = v0;                 // keep relu'd v for aggregates
            acc[mt][nt][3] = v1;
            g_v[(size_t)m0 * (HH*DD) + h * DD + dl]       = v0;
            g_v[(size_t)(m0 + 8) * (HH*DD) + h * DD + dl] = v1;
        }
        s0 += __shfl_xor_sync(0xFFFFFFFF, s0, 1);
        s0 += __shfl_xor_sync(0xFFFFFFFF, s0, 2);
        s1 += __shfl_xor_sync(0xFFFFFFFF, s1, 1);
        s1 += __shfl_xor_sync(0xFFFFFFFF, s1, 2);
        if (qd == 0) {
            sred[ml0][wn]     = s0;
            sred[ml0 + 8][wn] = s1;
        }
    }
    __syncthreads();
    if (tid < 256) {
        float s = sred[tid][0] + sred[tid][1] + sred[tid][2] + sred[tid][3];
        g_s[(bm + tid) * HH + h] = s;
        ssm[tid] = s;
    }
    __syncthreads();

    // ---- per-chunk aggregates (wm = chunk within the 256-row tile) ----
    float sr[4][2];
#pragma unroll
    for (int mt = 0; mt < 4; mt++) {
        sr[mt][0] = ssm[wm * 64 + mt * 16 + gq];
        sr[mt][1] = ssm[wm * 64 + mt * 16 + gq + 8];
    }
    float lm = -1e30f;
#pragma unroll
    for (int mt = 0; mt < 4; mt++) {
        lm = fmaxf(lm, sr[mt][0]);
        lm = fmaxf(lm, sr[mt][1]);
    }
    lm = fmaxf(lm, __shfl_xor_sync(0xFFFFFFFF, lm, 4));
    lm = fmaxf(lm, __shfl_xor_sync(0xFFFFFFFF, lm, 8));
    lm = fmaxf(lm, __shfl_xor_sync(0xFFFFFFFF, lm, 16));

    float e[4][2];
    float lu = 0.f;
#pragma unroll
    for (int mt = 0; mt < 4; mt++) {
        e[mt][0] = __expf(sr[mt][0] - lm);
        e[mt][1] = __expf(sr[mt][1] - lm);
        lu += e[mt][0] + e[mt][1];
    }
    float wv[4] = {0.f, 0.f, 0.f, 0.f};
#pragma unroll
    for (int nt = 0; nt < 4; nt++)
#pragma unroll
        for (int mt = 0; mt < 4; mt++)
            wv[nt] += e[mt][0] * acc[mt][nt][1] + e[mt][1] * acc[mt][nt][3];
#pragma unroll
    for (int mask = 4; mask <= 16; mask <<= 1) {
        lu += __shfl_xor_sync(0xFFFFFFFF, lu, mask);
#pragma unroll
        for (int nt = 0; nt < 4; nt++)
            wv[nt] += __shfl_xor_sync(0xFFFFFFFF, wv[nt], mask);
    }
    const int crow = (bm >> 6) + wm;                       // global chunk row
    const int cidx = ((crow >> 6) * HH + h) * CC + (crow & 63);
    if (gq == 0) {
#pragma unroll
        for (int nt = 0; nt < 4; nt++)
            g_cw[cidx * DD + wn * 16 + nt * 4 + qd] = wv[nt];
        if (qd == 0 && wn == 0) { g_cm[cidx] = lm; g_cu[cidx] = lu; }
    }
}

// ---------------------------------------------------------------------------
// Scan phase B: exclusive scan over chunk aggregates, smem-staged.
// grid = B*H, 64 threads.
// ---------------------------------------------------------------------------
__global__ __launch_bounds__(64) void scanB() {
    __shared__ float scm[CC], scu[CC], scw[CC * DD];
    const int bh = blockIdx.x;
    const int d  = threadIdx.x;

    for (int c = 0; c < CC; c++)
        scw[c * DD + d] = g_cw[(bh * CC + c) * DD + d];
    scm[d] = g_cm[bh * CC + d];
    scu[d] = g_cu[bh * CC + d];
    __syncthreads();

    float mC = -1e30f, uC = 0.f, wC = 0.f;
    for (int c = 0; c < CC; c++) {
        const int idx = bh * CC + c;
        const float ma = scm[c];
        const float ua = scu[c];
        const float wa = scw[c * DD + d];
        g_cw[idx * DD + d] = wC;                    // exclusive prefix out
        if (d == 0) { g_cm[idx] = mC; g_cu[idx] = uC; }
        const float nm = fmaxf(mC, ma);
        const float ea = __expf(mC - nm);
        const float eb = __expf(ma - nm);
        uC = uC * ea + ua * eb;
        wC = wC * ea + wa * eb;
        mC = nm;
    }
}

// ---------------------------------------------------------------------------
// Scan phase C fused with head-reduction: out[b,t,d] = sum_h w/u.
// grid = B*C blocks, 256 threads (4 h-groups x 64 d). No atomics:
// per-hs partials in a 64KB dynamic smem slab, then 4-way sum.
// ---------------------------------------------------------------------------
__global__ __launch_bounds__(256) void scanCR(float* __restrict__ out) {
    extern __shared__ float accS[];                 // [4][LL][DD] = 64KB
    const int b  = blockIdx.x / CC;
    const int c  = blockIdx.x % CC;
    const int tid = threadIdx.x;
    const int hs = tid >> 6;                        // 0..3
    const int d  = tid & 63;
    const int t0 = c * LL;

    float m[4], u[4], w[4];
#pragma unroll
    for (int hi = 0; hi < 4; hi++) {
        const int h   = hs * 4 + hi;
        const int idx = (b * HH + h) * CC + c;
        m[hi] = g_cm[idx];
        u[hi] = g_cu[idx];
        w[hi] = g_cw[idx * DD + d];
    }
    float* slab = accS + (size_t)hs * LL * DD;
    for (int tt = 0; tt < LL; tt++) {
        const int mrow = b * TT + t0 + tt;
        float sum = 0.f;
#pragma unroll
        for (int hi = 0; hi < 4; hi++) {
            const int h = hs * 4 + hi;
            const float s = g_s[mrow * HH + h];
            const float v = g_v[(size_t)mrow * (HH*DD) + h * DD + d];
            const float nm = fmaxf(m[hi], s);
            const float a = __expf(m[hi] - nm);
            const float ex = __expf(s - nm);
            u[hi] = u[hi] * a + ex;
            w[hi] = w[hi] * a + ex * v;
            m[hi] = nm;
            sum += __fdividef(w[hi], u[hi]);
        }
        slab[tt * DD + d] = sum;
    }
    __syncthreads();
    for (int i = tid; i < LL * DD; i += 256) {
        const int tt = i >> 6, dd = i & 63;
        out[((size_t)b * TT + t0 + tt) * DD + dd] =
            accS[i] + accS[LL*DD + i] + accS[2*LL*DD + i] + accS[3*LL*DD + i];
    }
}

extern "C" void kernel_launch(void* const* d_in, const int* in_sizes, int n_in,
                              void* d_out, int out_size) {
    const float* X = (const float*)d_in[0];   // [B,T,DIN]
    const float* W = (const float*)d_in[1];   // [DIN, 2048]
    const float* q = (const float*)d_in[2];   // [H,D]
    float* out = (float*)d_out;               // [B,T,D]

    const int gemm_smem = STAGES * (int)STAGE_BYTES;     // 196608
    const int scan_smem = 4 * LL * DD * (int)sizeof(float); // 65536
    cudaFuncSetAttribute(gemm_mma, cudaFuncAttributeMaxDynamicSharedMemorySize,
                         gemm_smem);
    cudaFuncSetAttribute(scanCR, cudaFuncAttributeMaxDynamicSharedMemorySize,
                         scan_smem);

    convX<<<(MM * DIN) / (256 * 8), 256>>>(X);
    convW<<<dim3(NN / 32, DIN / 32), dim3(32, 8)>>>(W);
    gemm_mma<<<dim3(HH, MM / GBM), 512, gemm_smem>>>(q);
    scanB<<<BB * HH, 64>>>();
    scanCR<<<BB * CC, 256, scan_smem>>>(out);
}

// round 8
// speedup vs baseline: 6.3067x; 1.0896x over previous
#include <cuda_runtime.h>
#include <cuda_fp16.h>
#include <math.h>
#include <stdint.h>

// Problem constants
#define BB   4
#define TT   4096
#define DIN  1024
#define HH   16
#define DD   64
#define MM   (BB*TT)        // 16384
#define NN   (HH*DD*2)      // 2048
#define CC   64             // scan chunks per (b,h)
#define LL   (TT/CC)        // 64

// GEMM tiling: 256x128x64, 512 threads (16 warps, 4x4, warp tile 64x32)
#define GBM 256
#define GBN 128
#define GBK 64
#define STAGES 4
#define KITERS (DIN/GBK)    // 16
#define STAGE_BYTES 49152u  // 32KB A + 16KB B

// ---------------------------------------------------------------------------
// Scratch (device globals; no allocation allowed)
// ---------------------------------------------------------------------------
__device__ __half g_Xh[(size_t)MM * DIN];      // 32 MiB
__device__ __half g_Wt[(size_t)NN * DIN];      // 4 MiB  (transposed W: [n][k])
__device__ __half g_vh[(size_t)MM * (HH*DD)];  // 32 MiB packed relu(v) fp16
__device__ float  g_s[MM * HH];                // 1 MiB
__device__ float  g_cm[BB*HH*CC];
__device__ float  g_cu[BB*HH*CC];
__device__ float  g_cw[BB*HH*CC*DD];

// ---------------------------------------------------------------------------
// asm helpers
// ---------------------------------------------------------------------------
__device__ __forceinline__ uint32_t smem_u32(const void* p) {
    uint32_t a;
    asm("{ .reg .u64 t; cvta.to.shared.u64 t, %1; cvt.u32.u64 %0, t; }" : "=r"(a) : "l"(p));
    return a;
}
__device__ __forceinline__ void cp16(uint32_t dst, const void* src) {
    asm volatile("cp.async.cg.shared.global [%0], [%1], 16;" :: "r"(dst), "l"(src));
}
__device__ __forceinline__ void ldm4(uint32_t* r, uint32_t addr) {
    asm volatile("ldmatrix.sync.aligned.m8n8.x4.shared.b16 {%0,%1,%2,%3}, [%4];"
                 : "=r"(r[0]), "=r"(r[1]), "=r"(r[2]), "=r"(r[3]) : "r"(addr));
}
__device__ __forceinline__ void mma16816(float* c, const uint32_t* a, const uint32_t* b) {
    asm volatile("mma.sync.aligned.m16n8k16.row.col.f32.f16.f16.f32 "
                 "{%0,%1,%2,%3}, {%4,%5,%6,%7}, {%8,%9}, {%0,%1,%2,%3};"
                 : "+f"(c[0]), "+f"(c[1]), "+f"(c[2]), "+f"(c[3])
                 : "r"(a[0]), "r"(a[1]), "r"(a[2]), "r"(a[3]), "r"(b[0]), "r"(b[1]));
}

// ---------------------------------------------------------------------------
// Prep: X fp32 -> fp16 (8 floats / thread)
// ---------------------------------------------------------------------------
__global__ __launch_bounds__(256) void convX(const float* __restrict__ X) {
    size_t i = (size_t)blockIdx.x * 256 + threadIdx.x;   // < 2M
    const float4* src = (const float4*)X + i * 2;
    float4 x0 = src[0], x1 = src[1];
    __half2 h0 = __floats2half2_rn(x0.x, x0.y);
    __half2 h1 = __floats2half2_rn(x0.z, x0.w);
    __half2 h2 = __floats2half2_rn(x1.x, x1.y);
    __half2 h3 = __floats2half2_rn(x1.z, x1.w);
    uint4 o;
    o.x = *(uint32_t*)&h0; o.y = *(uint32_t*)&h1;
    o.z = *(uint32_t*)&h2; o.w = *(uint32_t*)&h3;
    ((uint4*)g_Xh)[i] = o;
}

// Prep: W [K=1024][N=2048] fp32 -> g_Wt fp16 [N][K]
__global__ void convW(const float* __restrict__ W) {
    __shared__ float tile[32][33];
    const int n0 = blockIdx.x * 32, k0 = blockIdx.y * 32;
    const int tx = threadIdx.x, ty = threadIdx.y;        // 32 x 8
    for (int r = ty; r < 32; r += 8)
        tile[r][tx] = W[(size_t)(k0 + r) * NN + n0 + tx];
    __syncthreads();
    for (int r = ty; r < 32; r += 8)
        g_Wt[(size_t)(n0 + r) * DIN + k0 + tx] = __float2half(tile[tx][r]);
}

// ---------------------------------------------------------------------------
// GEMM via mma.sync: kv = relu(X @ W); fused: de-interleave v (fp16, smem-
// staged coalesced store), s = q.relu(k), and per-chunk scan aggregates.
// CTA 256x128x64, 512 threads, 4-stage cp.async.
// blockIdx.x = head h, blockIdx.y = M-tile (256 rows = 4 scan chunks).
// ---------------------------------------------------------------------------
__device__ __forceinline__ void issue_stage(uint32_t sb, int stage, int kc,
                                            int bm, int bn, int tid) {
    const uint32_t so = sb + (uint32_t)stage * STAGE_BYTES;
    const int k0 = kc * GBK;
#pragma unroll
    for (int i = 0; i < 4; i++) {                        // A: 256 rows x 128B
        int idx = tid + i * 512;
        int row = idx >> 3, ch = idx & 7;
        cp16(so + row * 128 + ((uint32_t)(ch ^ (row & 7)) << 4),
             g_Xh + (size_t)(bm + row) * DIN + k0 + ch * 8);
    }
#pragma unroll
    for (int i = 0; i < 2; i++) {                        // B: 128 rows x 128B
        int idx = tid + i * 512;
        int row = idx >> 3, ch = idx & 7;
        cp16(so + 32768u + row * 128 + ((uint32_t)(ch ^ (row & 7)) << 4),
             g_Wt + (size_t)(bn + row) * DIN + k0 + ch * 8);
    }
}

__global__ __launch_bounds__(512) void gemm_mma(const float* __restrict__ qk) {
    extern __shared__ char sm[];
    __shared__ float sred[256][4];
    __shared__ float ssm[256];
    const uint32_t sb = smem_u32(sm);
    const int tid = threadIdx.x;
    const int wid = tid >> 5, lane = tid & 31;
    const int wm = wid >> 2, wn = wid & 3;               // 4 x 4 warps
    const int h  = blockIdx.x;
    const int bn = h << 7;
    const int bm = blockIdx.y * GBM;

    float acc[4][4][4];
#pragma unroll
    for (int a = 0; a < 4; a++)
#pragma unroll
        for (int b = 0; b < 4; b++)
#pragma unroll
            for (int c = 0; c < 4; c++) acc[a][b][c] = 0.f;

    // ldmatrix per-thread geometry
    const int arow = lane & 15;
    const int asel = lane >> 4;
    const int asw  = arow & 7;
    const int brow = (lane & 7) | (((lane >> 4) & 1) << 3);
    const int bsel = (lane >> 3) & 1;
    const int bsw  = brow & 7;
    uint32_t a_off[4], b_off[2];
#pragma unroll
    for (int mt = 0; mt < 4; mt++) a_off[mt] = (uint32_t)(wm * 64 + mt * 16 + arow) * 128;
#pragma unroll
    for (int bt = 0; bt < 2; bt++) b_off[bt] = 32768u + (uint32_t)(wn * 32 + bt * 16 + brow) * 128;

    // pipeline prologue
    for (int s = 0; s < STAGES - 1; s++) {
        issue_stage(sb, s, s, bm, bn, tid);
        asm volatile("cp.async.commit_group;" ::: "memory");
    }

    for (int kc = 0; kc < KITERS; kc++) {
        asm volatile("cp.async.wait_group 2;" ::: "memory");
        __syncthreads();

        if (kc + STAGES - 1 < KITERS)
            issue_stage(sb, (kc + STAGES - 1) & (STAGES - 1), kc + STAGES - 1, bm, bn, tid);
        asm volatile("cp.async.commit_group;" ::: "memory");

        const uint32_t so = sb + (uint32_t)(kc & (STAGES - 1)) * STAGE_BYTES;
#pragma unroll
        for (int ks = 0; ks < 4; ks++) {
            uint32_t af[4][4], bf[2][4];
#pragma unroll
            for (int mt = 0; mt < 4; mt++)
                ldm4(af[mt], so + a_off[mt] + ((uint32_t)(((ks << 1) | asel) ^ asw) << 4));
#pragma unroll
            for (int bt = 0; bt < 2; bt++)
                ldm4(bf[bt], so + b_off[bt] + ((uint32_t)(((ks << 1) | bsel) ^ bsw) << 4));
#pragma unroll
            for (int mt = 0; mt < 4; mt++) {
                mma16816(acc[mt][0], af[mt], &bf[0][0]);
                mma16816(acc[mt][1], af[mt], &bf[0][2]);
                mma16816(acc[mt][2], af[mt], &bf[1][0]);
                mma16816(acc[mt][3], af[mt], &bf[1][2]);
            }
        }
    }

    // ------------- fused epilogue -------------
    // c0,c1 = (k,v) at row gq; c2,c3 = (k,v) at row gq+8; d = wn*16+nt*4+qd
    const int gq = lane >> 2, qd = lane & 3;
    float qv[4];
#pragma unroll
    for (int nt = 0; nt < 4; nt++)
        qv[nt] = __ldg(&qk[h * DD + wn * 16 + nt * 4 + qd]);

#pragma unroll
    for (int mt = 0; mt < 4; mt++) {
        const int ml0 = wm * 64 + mt * 16 + gq;
        float s0 = 0.f, s1 = 0.f;
#pragma unroll
        for (int nt = 0; nt < 4; nt++) {
            float k0 = fmaxf(acc[mt][nt][0], 0.f), v0 = fmaxf(acc[mt][nt][1], 0.f);
            float k1 = fmaxf(acc[mt][nt][2], 0.f), v1 = fmaxf(acc[mt][nt][3], 0.f);
            s0 += qv[nt] * k0;
            s1 += qv[nt] * k1;
            acc[mt][nt][1] = v0;                 // keep relu'd v for aggregates
            acc[mt][nt][3] = v1;
        }
        s0 += __shfl_xor_sync(0xFFFFFFFF, s0, 1);
        s0 += __shfl_xor_sync(0xFFFFFFFF, s0, 2);
        s1 += __shfl_xor_sync(0xFFFFFFFF, s1, 1);
        s1 += __shfl_xor_sync(0xFFFFFFFF, s1, 2);
        if (qd == 0) {
            sred[ml0][wn]     = s0;
            sred[ml0 + 8][wn] = s1;
        }
    }
    __syncthreads();
    if (tid < 256) {
        float s = sred[tid][0] + sred[tid][1] + sred[tid][2] + sred[tid][3];
        g_s[(bm + tid) * HH + h] = s;
        ssm[tid] = s;
    }
    __syncthreads();

    // ---- per-chunk aggregates (wm = chunk within the 256-row tile) ----
    float sr[4][2];
#pragma unroll
    for (int mt = 0; mt < 4; mt++) {
        sr[mt][0] = ssm[wm * 64 + mt * 16 + gq];
        sr[mt][1] = ssm[wm * 64 + mt * 16 + gq + 8];
    }
    float lm = -1e30f;
#pragma unroll
    for (int mt = 0; mt < 4; mt++) {
        lm = fmaxf(lm, sr[mt][0]);
        lm = fmaxf(lm, sr[mt][1]);
    }
    lm = fmaxf(lm, __shfl_xor_sync(0xFFFFFFFF, lm, 4));
    lm = fmaxf(lm, __shfl_xor_sync(0xFFFFFFFF, lm, 8));
    lm = fmaxf(lm, __shfl_xor_sync(0xFFFFFFFF, lm, 16));

    float e[4][2];
    float lu = 0.f;
#pragma unroll
    for (int mt = 0; mt < 4; mt++) {
        e[mt][0] = __expf(sr[mt][0] - lm);
        e[mt][1] = __expf(sr[mt][1] - lm);
        lu += e[mt][0] + e[mt][1];
    }
    float wv[4] = {0.f, 0.f, 0.f, 0.f};
#pragma unroll
    for (int nt = 0; nt < 4; nt++)
#pragma unroll
        for (int mt = 0; mt < 4; mt++)
            wv[nt] += e[mt][0] * acc[mt][nt][1] + e[mt][1] * acc[mt][nt][3];
#pragma unroll
    for (int mask = 4; mask <= 16; mask <<= 1) {
        lu += __shfl_xor_sync(0xFFFFFFFF, lu, mask);
#pragma unroll
        for (int nt = 0; nt < 4; nt++)
            wv[nt] += __shfl_xor_sync(0xFFFFFFFF, wv[nt], mask);
    }
    const int crow = (bm >> 6) + wm;                       // global chunk row
    const int cidx = ((crow >> 6) * HH + h) * CC + (crow & 63);
    if (gq == 0) {
#pragma unroll
        for (int nt = 0; nt < 4; nt++)
            g_cw[cidx * DD + wn * 16 + nt * 4 + qd] = wv[nt];
        if (qd == 0 && wn == 0) { g_cm[cidx] = lm; g_cu[cidx] = lu; }
    }

    // ---- stage v (fp16) into now-idle pipeline smem, then coalesced write ----
    // layout: [256 rows][72 halfs] (144B stride: 16B-aligned, bank-shift 4/row)
    __half* svh = (__half*)sm;
#pragma unroll
    for (int mt = 0; mt < 4; mt++) {
        const int ml0 = wm * 64 + mt * 16 + gq;
#pragma unroll
        for (int nt = 0; nt < 4; nt++) {
            const int dl = wn * 16 + nt * 4 + qd;
            svh[ml0 * 72 + dl]       = __float2half_rn(acc[mt][nt][1]);
            svh[(ml0 + 8) * 72 + dl] = __float2half_rn(acc[mt][nt][3]);
        }
    }
    __syncthreads();
    const uint4* src4 = (const uint4*)sm;
#pragma unroll
    for (int i = 0; i < 4; i++) {
        int idx = tid + i * 512;                 // < 2048
        int row = idx >> 3, part = idx & 7;
        *((uint4*)(g_vh + (size_t)(bm + row) * (HH*DD) + h * DD + part * 8)) =
            src4[row * 9 + part];
    }
}

// ---------------------------------------------------------------------------
// Scan phase B: exclusive scan over chunk aggregates, smem-staged.
// grid = B*H, 256 threads (192 only help the coalesced staging load).
// ---------------------------------------------------------------------------
__global__ __launch_bounds__(256) void scanB() {
    __shared__ float scm[CC], scu[CC], scw[CC * DD];
    const int bh = blockIdx.x;
    const int tid = threadIdx.x;

    for (int i = tid; i < CC * DD; i += 256)
        scw[i] = g_cw[(size_t)bh * CC * DD + i];
    if (tid < CC) {
        scm[tid] = g_cm[bh * CC + tid];
        scu[tid] = g_cu[bh * CC + tid];
    }
    __syncthreads();

    if (tid < DD) {
        const int d = tid;
        float mC = -1e30f, uC = 0.f, wC = 0.f;
        for (int c = 0; c < CC; c++) {
            const int idx = bh * CC + c;
            const float ma = scm[c];
            const float ua = scu[c];
            const float wa = scw[c * DD + d];
            g_cw[idx * DD + d] = wC;                // exclusive prefix out
            if (d == 0) { g_cm[idx] = mC; g_cu[idx] = uC; }
            if (ma > mC) {
                const float a = __expf(mC - ma);
                uC = uC * a + ua;
                wC = wC * a + wa;
                mC = ma;
            } else {
                const float eb = __expf(ma - mC);
                uC += ua * eb;
                wC += wa * eb;
            }
        }
    }
}

// ---------------------------------------------------------------------------
// Scan phase C fused with head-reduction: out[b,t,d] = sum_h w/u.
// grid = B*C blocks, 256 threads (4 h-groups x 64 d). One exp per step
// (warp-uniform branch), s staged in smem, v fp16.
// ---------------------------------------------------------------------------
__global__ __launch_bounds__(256) void scanCR(float* __restrict__ out) {
    extern __shared__ float dyn[];                  // slab 64KB + s_sm 4KB
    float* slab = dyn;
    float* s_sm = dyn + 4 * LL * DD;
    const int b  = blockIdx.x / CC;
    const int c  = blockIdx.x % CC;
    const int tid = threadIdx.x;
    const int hs = tid >> 6;                        // 0..3
    const int d  = tid & 63;
    const int t0 = c * LL;

    // stage s block: contiguous 1024 floats
    ((float4*)s_sm)[tid] = ((const float4*)(g_s + (size_t)(b * TT + t0) * HH))[tid];
    __syncthreads();

    float m[4], u[4], w[4];
#pragma unroll
    for (int hi = 0; hi < 4; hi++) {
        const int h   = hs * 4 + hi;
        const int idx = (b * HH + h) * CC + c;
        m[hi] = g_cm[idx];
        u[hi] = g_cu[idx];
        w[hi] = g_cw[idx * DD + d];
    }
    float* myslab = slab + hs * LL * DD;
    for (int tt = 0; tt < LL; tt++) {
        const __half* vrow = g_vh + (size_t)(b * TT + t0 + tt) * (HH*DD);
        float sum = 0.f;
#pragma unroll
        for (int hi = 0; hi < 4; hi++) {
            const int h = hs * 4 + hi;
            const float s = s_sm[tt * HH + h];
            const float v = __half2float(vrow[h * DD + d]);
            if (s > m[hi]) {                        // warp-uniform branch
                const float a = __expf(m[hi] - s);
                u[hi] = u[hi] * a + 1.f;
                w[hi] = w[hi] * a + v;
                m[hi] = s;
            } else {
                const float ex = __expf(s - m[hi]);
                u[hi] += ex;
                w[hi] += ex * v;
            }
            sum += __fdividef(w[hi], u[hi]);
        }
        myslab[tt * DD + d] = sum;
    }
    __syncthreads();
    for (int i = tid; i < LL * DD; i += 256) {
        const int tt = i >> 6, dd = i & 63;
        out[((size_t)b * TT + t0 + tt) * DD + dd] =
            slab[i] + slab[LL*DD + i] + slab[2*LL*DD + i] + slab[3*LL*DD + i];
    }
}

extern "C" void kernel_launch(void* const* d_in, const int* in_sizes, int n_in,
                              void* d_out, int out_size) {
    const float* X = (const float*)d_in[0];   // [B,T,DIN]
    const float* W = (const float*)d_in[1];   // [DIN, 2048]
    const float* q = (const float*)d_in[2];   // [H,D]
    float* out = (float*)d_out;               // [B,T,D]

    const int gemm_smem = STAGES * (int)STAGE_BYTES;        // 196608
    const int scan_smem = (4 * LL * DD + LL * HH) * (int)sizeof(float); // 69632
    cudaFuncSetAttribute(gemm_mma, cudaFuncAttributeMaxDynamicSharedMemorySize,
                         gemm_smem);
    cudaFuncSetAttribute(scanCR, cudaFuncAttributeMaxDynamicSharedMemorySize,
                         scan_smem);

    convX<<<(MM * DIN) / (256 * 8), 256>>>(X);
    convW<<<dim3(NN / 32, DIN / 32), dim3(32, 8)>>>(W);
    gemm_mma<<<dim3(HH, MM / GBM), 512, gemm_smem>>>(q);
    scanB<<<BB * HH, 256>>>();
    scanCR<<<BB * CC, 256, scan_smem>>>(out);
}

// round 9
// speedup vs baseline: 6.5167x; 1.0333x over previous
#include <cuda_runtime.h>
#include <cuda_fp16.h>
#include <math.h>
#include <stdint.h>

// Problem constants
#define BB   4
#define TT   4096
#define DIN  1024
#define HH   16
#define DD   64
#define MM   (BB*TT)        // 16384
#define NN   (HH*DD*2)      // 2048
#define CC   64             // scan chunks per (b,h)
#define LL   (TT/CC)        // 64

// GEMM tiling: 256x128x64, 512 threads (16 warps, 4x4, warp tile 64x32)
#define GBM 256
#define GBN 128
#define GBK 64
#define STAGES 4
#define KITERS (DIN/GBK)    // 16
#define STAGE_BYTES 49152u  // 32KB A + 16KB B

// ---------------------------------------------------------------------------
// Scratch (device globals; no allocation allowed)
// ---------------------------------------------------------------------------
__device__ __half g_Xh[(size_t)MM * DIN];      // 32 MiB
__device__ __half g_Wt[(size_t)NN * DIN];      // 4 MiB  (transposed W: [n][k])
__device__ __half g_vh[(size_t)MM * (HH*DD)];  // 32 MiB packed relu(v) fp16
__device__ float  g_s[MM * HH];                // 1 MiB
__device__ float  g_cm[BB*HH*CC];
__device__ float  g_cu[BB*HH*CC];
__device__ float  g_cw[BB*HH*CC*DD];

// ---------------------------------------------------------------------------
// asm helpers
// ---------------------------------------------------------------------------
__device__ __forceinline__ uint32_t smem_u32(const void* p) {
    uint32_t a;
    asm("{ .reg .u64 t; cvta.to.shared.u64 t, %1; cvt.u32.u64 %0, t; }" : "=r"(a) : "l"(p));
    return a;
}
__device__ __forceinline__ void cp16(uint32_t dst, const void* src) {
    asm volatile("cp.async.cg.shared.global [%0], [%1], 16;" :: "r"(dst), "l"(src));
}
__device__ __forceinline__ void ldm4(uint32_t* r, uint32_t addr) {
    asm volatile("ldmatrix.sync.aligned.m8n8.x4.shared.b16 {%0,%1,%2,%3}, [%4];"
                 : "=r"(r[0]), "=r"(r[1]), "=r"(r[2]), "=r"(r[3]) : "r"(addr));
}
__device__ __forceinline__ void mma16816(float* c, const uint32_t* a, const uint32_t* b) {
    asm volatile("mma.sync.aligned.m16n8k16.row.col.f32.f16.f16.f32 "
                 "{%0,%1,%2,%3}, {%4,%5,%6,%7}, {%8,%9}, {%0,%1,%2,%3};"
                 : "+f"(c[0]), "+f"(c[1]), "+f"(c[2]), "+f"(c[3])
                 : "r"(a[0]), "r"(a[1]), "r"(a[2]), "r"(a[3]), "r"(b[0]), "r"(b[1]));
}

// ---------------------------------------------------------------------------
// Fused prep: blocks [0, 8192) convert X fp32 -> fp16 (8 floats / thread);
// blocks [8192, 10240) transpose+convert W [K][N] fp32 -> g_Wt fp16 [N][K].
// ---------------------------------------------------------------------------
__global__ __launch_bounds__(256) void convXW(const float* __restrict__ X,
                                              const float* __restrict__ W) {
    const int tid = threadIdx.x;
    if (blockIdx.x < 8192) {
        size_t i = (size_t)blockIdx.x * 256 + tid;       // < 2M
        const float4* src = (const float4*)X + i * 2;
        float4 x0 = src[0], x1 = src[1];
        __half2 h0 = __floats2half2_rn(x0.x, x0.y);
        __half2 h1 = __floats2half2_rn(x0.z, x0.w);
        __half2 h2 = __floats2half2_rn(x1.x, x1.y);
        __half2 h3 = __floats2half2_rn(x1.z, x1.w);
        uint4 o;
        o.x = *(uint32_t*)&h0; o.y = *(uint32_t*)&h1;
        o.z = *(uint32_t*)&h2; o.w = *(uint32_t*)&h3;
        ((uint4*)g_Xh)[i] = o;
    } else {
        __shared__ float tile[32][33];
        const int bw = blockIdx.x - 8192;                // < 2048
        const int n0 = (bw & 63) * 32, k0 = (bw >> 6) * 32;
        const int tx = tid & 31, ty = tid >> 5;          // 32 x 8
        for (int r = ty; r < 32; r += 8)
            tile[r][tx] = W[(size_t)(k0 + r) * NN + n0 + tx];
        __syncthreads();
        for (int r = ty; r < 32; r += 8)
            g_Wt[(size_t)(n0 + r) * DIN + k0 + tx] = __float2half(tile[tx][r]);
    }
}

// ---------------------------------------------------------------------------
// GEMM via mma.sync: kv = relu(X @ W); fused: de-interleave v (fp16, smem-
// staged coalesced store), s = q.relu(k), and per-chunk scan aggregates.
// CTA 256x128x64, 512 threads, 4-stage cp.async, B-fragment double buffer.
// blockIdx.x = head h, blockIdx.y = M-tile (256 rows = 4 scan chunks).
// ---------------------------------------------------------------------------
__device__ __forceinline__ void issue_stage(uint32_t sb, int stage, int kc,
                                            int bm, int bn, int tid) {
    const uint32_t so = sb + (uint32_t)stage * STAGE_BYTES;
    const int k0 = kc * GBK;
#pragma unroll
    for (int i = 0; i < 4; i++) {                        // A: 256 rows x 128B
        int idx = tid + i * 512;
        int row = idx >> 3, ch = idx & 7;
        cp16(so + row * 128 + ((uint32_t)(ch ^ (row & 7)) << 4),
             g_Xh + (size_t)(bm + row) * DIN + k0 + ch * 8);
    }
#pragma unroll
    for (int i = 0; i < 2; i++) {                        // B: 128 rows x 128B
        int idx = tid + i * 512;
        int row = idx >> 3, ch = idx & 7;
        cp16(so + 32768u + row * 128 + ((uint32_t)(ch ^ (row & 7)) << 4),
             g_Wt + (size_t)(bn + row) * DIN + k0 + ch * 8);
    }
}

__global__ __launch_bounds__(512) void gemm_mma(const float* __restrict__ qk) {
    extern __shared__ char sm[];
    __shared__ float sred[256][4];
    __shared__ float ssm[256];
    const uint32_t sb = smem_u32(sm);
    const int tid = threadIdx.x;
    const int wid = tid >> 5, lane = tid & 31;
    const int wm = wid >> 2, wn = wid & 3;               // 4 x 4 warps
    const int h  = blockIdx.x;
    const int bn = h << 7;
    const int bm = blockIdx.y * GBM;

    float acc[4][4][4];
#pragma unroll
    for (int a = 0; a < 4; a++)
#pragma unroll
        for (int b = 0; b < 4; b++)
#pragma unroll
            for (int c = 0; c < 4; c++) acc[a][b][c] = 0.f;

    // ldmatrix per-thread geometry
    const int arow = lane & 15;
    const int asel = lane >> 4;
    const int asw  = arow & 7;
    const int brow = (lane & 7) | (((lane >> 4) & 1) << 3);
    const int bsel = (lane >> 3) & 1;
    const int bsw  = brow & 7;
    uint32_t a_off[4], b_off[2];
#pragma unroll
    for (int mt = 0; mt < 4; mt++) a_off[mt] = (uint32_t)(wm * 64 + mt * 16 + arow) * 128;
#pragma unroll
    for (int bt = 0; bt < 2; bt++) b_off[bt] = 32768u + (uint32_t)(wn * 32 + bt * 16 + brow) * 128;

    // pipeline prologue
    for (int s = 0; s < STAGES - 1; s++) {
        issue_stage(sb, s, s, bm, bn, tid);
        asm volatile("cp.async.commit_group;" ::: "memory");
    }

    for (int kc = 0; kc < KITERS; kc++) {
        asm volatile("cp.async.wait_group 2;" ::: "memory");
        __syncthreads();

        if (kc + STAGES - 1 < KITERS)
            issue_stage(sb, (kc + STAGES - 1) & (STAGES - 1), kc + STAGES - 1, bm, bn, tid);
        asm volatile("cp.async.commit_group;" ::: "memory");

        const uint32_t so = sb + (uint32_t)(kc & (STAGES - 1)) * STAGE_BYTES;
        // B-fragment double buffer: prefetch ks+1 while issuing mma for ks
        uint32_t bf[2][2][4];
#pragma unroll
        for (int bt = 0; bt < 2; bt++)
            ldm4(bf[0][bt], so + b_off[bt] + ((uint32_t)(bsel ^ bsw) << 4));
#pragma unroll
        for (int ks = 0; ks < 4; ks++) {
            uint32_t af[4][4];
#pragma unroll
            for (int mt = 0; mt < 4; mt++)
                ldm4(af[mt], so + a_off[mt] + ((uint32_t)(((ks << 1) | asel) ^ asw) << 4));
            if (ks < 3) {
#pragma unroll
                for (int bt = 0; bt < 2; bt++)
                    ldm4(bf[(ks + 1) & 1][bt],
                         so + b_off[bt] + ((uint32_t)((((ks + 1) << 1) | bsel) ^ bsw) << 4));
            }
            const uint32_t (*bcur)[4] = bf[ks & 1];
#pragma unroll
            for (int mt = 0; mt < 4; mt++) {
                mma16816(acc[mt][0], af[mt], &bcur[0][0]);
                mma16816(acc[mt][1], af[mt], &bcur[0][2]);
                mma16816(acc[mt][2], af[mt], &bcur[1][0]);
                mma16816(acc[mt][3], af[mt], &bcur[1][2]);
            }
        }
    }

    // ------------- fused epilogue -------------
    // c0,c1 = (k,v) at row gq; c2,c3 = (k,v) at row gq+8; d = wn*16+nt*4+qd
    const int gq = lane >> 2, qd = lane & 3;
    float qv[4];
#pragma unroll
    for (int nt = 0; nt < 4; nt++)
        qv[nt] = __ldg(&qk[h * DD + wn * 16 + nt * 4 + qd]);

#pragma unroll
    for (int mt = 0; mt < 4; mt++) {
        const int ml0 = wm * 64 + mt * 16 + gq;
        float s0 = 0.f, s1 = 0.f;
#pragma unroll
        for (int nt = 0; nt < 4; nt++) {
            float k0 = fmaxf(acc[mt][nt][0], 0.f), v0 = fmaxf(acc[mt][nt][1], 0.f);
            float k1 = fmaxf(acc[mt][nt][2], 0.f), v1 = fmaxf(acc[mt][nt][3], 0.f);
            s0 += qv[nt] * k0;
            s1 += qv[nt] * k1;
            acc[mt][nt][1] = v0;                 // keep relu'd v for aggregates
            acc[mt][nt][3] = v1;
        }
        s0 += __shfl_xor_sync(0xFFFFFFFF, s0, 1);
        s0 += __shfl_xor_sync(0xFFFFFFFF, s0, 2);
        s1 += __shfl_xor_sync(0xFFFFFFFF, s1, 1);
        s1 += __shfl_xor_sync(0xFFFFFFFF, s1, 2);
        if (qd == 0) {
            sred[ml0][wn]     = s0;
            sred[ml0 + 8][wn] = s1;
        }
    }
    __syncthreads();
    if (tid < 256) {
        float s = sred[tid][0] + sred[tid][1] + sred[tid][2] + sred[tid][3];
        g_s[(bm + tid) * HH + h] = s;
        ssm[tid] = s;
    }
    __syncthreads();

    // ---- per-chunk aggregates (wm = chunk within the 256-row tile) ----
    float sr[4][2];
#pragma unroll
    for (int mt = 0; mt < 4; mt++) {
        sr[mt][0] = ssm[wm * 64 + mt * 16 + gq];
        sr[mt][1] = ssm[wm * 64 + mt * 16 + gq + 8];
    }
    float lm = -1e30f;
#pragma unroll
    for (int mt = 0; mt < 4; mt++) {
        lm = fmaxf(lm, sr[mt][0]);
        lm = fmaxf(lm, sr[mt][1]);
    }
    lm = fmaxf(lm, __shfl_xor_sync(0xFFFFFFFF, lm, 4));
    lm = fmaxf(lm, __shfl_xor_sync(0xFFFFFFFF, lm, 8));
    lm = fmaxf(lm, __shfl_xor_sync(0xFFFFFFFF, lm, 16));

    float e[4][2];
    float lu = 0.f;
#pragma unroll
    for (int mt = 0; mt < 4; mt++) {
        e[mt][0] = __expf(sr[mt][0] - lm);
        e[mt][1] = __expf(sr[mt][1] - lm);
        lu += e[mt][0] + e[mt][1];
    }
    float wv[4] = {0.f, 0.f, 0.f, 0.f};
#pragma unroll
    for (int nt = 0; nt < 4; nt++)
#pragma unroll
        for (int mt = 0; mt < 4; mt++)
            wv[nt] += e[mt][0] * acc[mt][nt][1] + e[mt][1] * acc[mt][nt][3];
#pragma unroll
    for (int mask = 4; mask <= 16; mask <<= 1) {
        lu += __shfl_xor_sync(0xFFFFFFFF, lu, mask);
#pragma unroll
        for (int nt = 0; nt < 4; nt++)
            wv[nt] += __shfl_xor_sync(0xFFFFFFFF, wv[nt], mask);
    }
    const int crow = (bm >> 6) + wm;                       // global chunk row
    const int cidx = ((crow >> 6) * HH + h) * CC + (crow & 63);
    if (gq == 0) {
#pragma unroll
        for (int nt = 0; nt < 4; nt++)
            g_cw[cidx * DD + wn * 16 + nt * 4 + qd] = wv[nt];
        if (qd == 0 && wn == 0) { g_cm[cidx] = lm; g_cu[cidx] = lu; }
    }

    // ---- stage v (fp16) into now-idle pipeline smem, then coalesced write ----
    // layout: [256 rows][72 halfs] (144B stride: 16B-aligned, bank-shift 4/row)
    __half* svh = (__half*)sm;
#pragma unroll
    for (int mt = 0; mt < 4; mt++) {
        const int ml0 = wm * 64 + mt * 16 + gq;
#pragma unroll
        for (int nt = 0; nt < 4; nt++) {
            const int dl = wn * 16 + nt * 4 + qd;
            svh[ml0 * 72 + dl]       = __float2half_rn(acc[mt][nt][1]);
            svh[(ml0 + 8) * 72 + dl] = __float2half_rn(acc[mt][nt][3]);
        }
    }
    __syncthreads();
    const uint4* src4 = (const uint4*)sm;
#pragma unroll
    for (int i = 0; i < 4; i++) {
        int idx = tid + i * 512;                 // < 2048
        int row = idx >> 3, part = idx & 7;
        *((uint4*)(g_vh + (size_t)(bm + row) * (HH*DD) + h * DD + part * 8)) =
            src4[row * 9 + part];
    }
}

// ---------------------------------------------------------------------------
// Scan phase B: exclusive scan over chunk aggregates, smem-staged.
// grid = B*H, 64 threads (measured faster than 256-thread variant).
// ---------------------------------------------------------------------------
__global__ __launch_bounds__(64) void scanB() {
    __shared__ float scm[CC], scu[CC], scw[CC * DD];
    const int bh = blockIdx.x;
    const int d  = threadIdx.x;

    for (int c = 0; c < CC; c++)
        scw[c * DD + d] = g_cw[(bh * CC + c) * DD + d];
    scm[d] = g_cm[bh * CC + d];
    scu[d] = g_cu[bh * CC + d];
    __syncthreads();

    float mC = -1e30f, uC = 0.f, wC = 0.f;
    for (int c = 0; c < CC; c++) {
        const int idx = bh * CC + c;
        const float ma = scm[c];
        const float ua = scu[c];
        const float wa = scw[c * DD + d];
        g_cw[idx * DD + d] = wC;                    // exclusive prefix out
        if (d == 0) { g_cm[idx] = mC; g_cu[idx] = uC; }
        if (ma > mC) {
            const float a = __expf(mC - ma);
            uC = uC * a + ua;
            wC = wC * a + wa;
            mC = ma;
        } else {
            const float eb = __expf(ma - mC);
            uC += ua * eb;
            wC += wa * eb;
        }
    }
}

// ---------------------------------------------------------------------------
// Scan phase C fused with head-reduction: out[b,t,d] = sum_h w/u.
// grid = B*C blocks, 256 threads (4 h-groups x 64 d). One exp per step
// (warp-uniform branch), s staged in smem, v fp16.
// ---------------------------------------------------------------------------
__global__ __launch_bounds__(256) void scanCR(float* __restrict__ out) {
    extern __shared__ float dyn[];                  // slab 64KB + s_sm 4KB
    float* slab = dyn;
    float* s_sm = dyn + 4 * LL * DD;
    const int b  = blockIdx.x / CC;
    const int c  = blockIdx.x % CC;
    const int tid = threadIdx.x;
    const int hs = tid >> 6;                        // 0..3
    const int d  = tid & 63;
    const int t0 = c * LL;

    // stage s block: contiguous 1024 floats
    ((float4*)s_sm)[tid] = ((const float4*)(g_s + (size_t)(b * TT + t0) * HH))[tid];
    __syncthreads();

    float m[4], u[4], w[4];
#pragma unroll
    for (int hi = 0; hi < 4; hi++) {
        const int h   = hs * 4 + hi;
        const int idx = (b * HH + h) * CC + c;
        m[hi] = g_cm[idx];
        u[hi] = g_cu[idx];
        w[hi] = g_cw[idx * DD + d];
    }
    float* myslab = slab + hs * LL * DD;
    for (int tt = 0; tt < LL; tt++) {
        const __half* vrow = g_vh + (size_t)(b * TT + t0 + tt) * (HH*DD);
        float sum = 0.f;
#pragma unroll
        for (int hi = 0; hi < 4; hi++) {
            const int h = hs * 4 + hi;
            const float s = s_sm[tt * HH + h];
            const float v = __half2float(vrow[h * DD + d]);
            if (s > m[hi]) {                        // warp-uniform branch
                const float a = __expf(m[hi] - s);
                u[hi] = u[hi] * a + 1.f;
                w[hi] = w[hi] * a + v;
                m[hi] = s;
            } else {
                const float ex = __expf(s - m[hi]);
                u[hi] += ex;
                w[hi] += ex * v;
            }
            sum += __fdividef(w[hi], u[hi]);
        }
        myslab[tt * DD + d] = sum;
    }
    __syncthreads();
    for (int i = tid; i < LL * DD; i += 256) {
        const int tt = i >> 6, dd = i & 63;
        out[((size_t)b * TT + t0 + tt) * DD + dd] =
            slab[i] + slab[LL*DD + i] + slab[2*LL*DD + i] + slab[3*LL*DD + i];
    }
}

extern "C" void kernel_launch(void* const* d_in, const int* in_sizes, int n_in,
                              void* d_out, int out_size) {
    const float* X = (const float*)d_in[0];   // [B,T,DIN]
    const float* W = (const float*)d_in[1];   // [DIN, 2048]
    const float* q = (const float*)d_in[2];   // [H,D]
    float* out = (float*)d_out;               // [B,T,D]

    const int gemm_smem = STAGES * (int)STAGE_BYTES;        // 196608
    const int scan_smem = (4 * LL * DD + LL * HH) * (int)sizeof(float); // 69632
    cudaFuncSetAttribute(gemm_mma, cudaFuncAttributeMaxDynamicSharedMemorySize,
                         gemm_smem);
    cudaFuncSetAttribute(scanCR, cudaFuncAttributeMaxDynamicSharedMemorySize,
                         scan_smem);

    convXW<<<8192 + 2048, 256>>>(X, W);
    gemm_mma<<<dim3(HH, MM / GBM), 512, gemm_smem>>>(q);
    scanB<<<BB * HH, 64>>>();
    scanCR<<<BB * CC, 256, scan_smem>>>(out);
}

// round 10
// speedup vs baseline: 6.6158x; 1.0152x over previous
#include <cuda_runtime.h>
#include <cuda_fp16.h>
#include <math.h>
#include <stdint.h>

// Problem constants
#define BB   4
#define TT   4096
#define DIN  1024
#define HH   16
#define DD   64
#define MM   (BB*TT)        // 16384
#define NN   (HH*DD*2)      // 2048
#define CC   64             // scan chunks per (b,h)
#define LL   (TT/CC)        // 64

// GEMM tiling: 256x128x64, 512 threads (16 warps, 4x4, warp tile 64x32)
#define GBM 256
#define GBN 128
#define GBK 64
#define STAGES 4
#define KITERS (DIN/GBK)    // 16
#define STAGE_BYTES 49152u  // 32KB A + 16KB B

// ---------------------------------------------------------------------------
// Scratch (device globals; no allocation allowed)
// ---------------------------------------------------------------------------
__device__ __half g_Xh[(size_t)MM * DIN];      // 32 MiB
__device__ __half g_Wt[(size_t)NN * DIN];      // 4 MiB  (transposed W: [n][k])
__device__ __half g_vh[(size_t)MM * (HH*DD)];  // 32 MiB packed relu(v) fp16
__device__ float  g_s[MM * HH];                // 1 MiB
__device__ float  g_cm[BB*HH*CC];
__device__ float  g_cu[BB*HH*CC];
__device__ float  g_cw[BB*HH*CC*DD];

// ---------------------------------------------------------------------------
// asm helpers
// ---------------------------------------------------------------------------
__device__ __forceinline__ uint32_t smem_u32(const void* p) {
    uint32_t a;
    asm("{ .reg .u64 t; cvta.to.shared.u64 t, %1; cvt.u32.u64 %0, t; }" : "=r"(a) : "l"(p));
    return a;
}
__device__ __forceinline__ void cp16(uint32_t dst, const void* src) {
    asm volatile("cp.async.cg.shared.global [%0], [%1], 16;" :: "r"(dst), "l"(src));
}
__device__ __forceinline__ void ldm4(uint32_t* r, uint32_t addr) {
    asm volatile("ldmatrix.sync.aligned.m8n8.x4.shared.b16 {%0,%1,%2,%3}, [%4];"
                 : "=r"(r[0]), "=r"(r[1]), "=r"(r[2]), "=r"(r[3]) : "r"(addr));
}
__device__ __forceinline__ void mma16816(float* c, const uint32_t* a, const uint32_t* b) {
    asm volatile("mma.sync.aligned.m16n8k16.row.col.f32.f16.f16.f32 "
                 "{%0,%1,%2,%3}, {%4,%5,%6,%7}, {%8,%9}, {%0,%1,%2,%3};"
                 : "+f"(c[0]), "+f"(c[1]), "+f"(c[2]), "+f"(c[3])
                 : "r"(a[0]), "r"(a[1]), "r"(a[2]), "r"(a[3]), "r"(b[0]), "r"(b[1]));
}

// ---------------------------------------------------------------------------
// Fused prep: blocks [0, 8192) convert X fp32 -> fp16 (8 floats / thread);
// blocks [8192, 10240) transpose+convert W [K][N] fp32 -> g_Wt fp16 [N][K].
// ---------------------------------------------------------------------------
__global__ __launch_bounds__(256) void convXW(const float* __restrict__ X,
                                              const float* __restrict__ W) {
    const int tid = threadIdx.x;
    if (blockIdx.x < 8192) {
        size_t i = (size_t)blockIdx.x * 256 + tid;       // < 2M
        const float4* src = (const float4*)X + i * 2;
        float4 x0 = src[0], x1 = src[1];
        __half2 h0 = __floats2half2_rn(x0.x, x0.y);
        __half2 h1 = __floats2half2_rn(x0.z, x0.w);
        __half2 h2 = __floats2half2_rn(x1.x, x1.y);
        __half2 h3 = __floats2half2_rn(x1.z, x1.w);
        uint4 o;
        o.x = *(uint32_t*)&h0; o.y = *(uint32_t*)&h1;
        o.z = *(uint32_t*)&h2; o.w = *(uint32_t*)&h3;
        ((uint4*)g_Xh)[i] = o;
    } else {
        __shared__ float tile[32][33];
        const int bw = blockIdx.x - 8192;                // < 2048
        const int n0 = (bw & 63) * 32, k0 = (bw >> 6) * 32;
        const int tx = tid & 31, ty = tid >> 5;          // 32 x 8
        for (int r = ty; r < 32; r += 8)
            tile[r][tx] = W[(size_t)(k0 + r) * NN + n0 + tx];
        __syncthreads();
        for (int r = ty; r < 32; r += 8)
            g_Wt[(size_t)(n0 + r) * DIN + k0 + tx] = __float2half(tile[tx][r]);
    }
}

// ---------------------------------------------------------------------------
// GEMM via mma.sync: kv = relu(X @ W); fused: de-interleave v (fp16, smem-
// staged coalesced store), s = q.relu(k), and per-chunk scan aggregates.
// CTA 256x128x64, 512 threads, 4-stage cp.async, B-fragment double buffer.
// blockIdx.x = head h, blockIdx.y = M-tile (256 rows = 4 scan chunks).
// ---------------------------------------------------------------------------
__device__ __forceinline__ void issue_stage(uint32_t sb, int stage, int kc,
                                            int bm, int bn, int tid) {
    const uint32_t so = sb + (uint32_t)stage * STAGE_BYTES;
    const int k0 = kc * GBK;
#pragma unroll
    for (int i = 0; i < 4; i++) {                        // A: 256 rows x 128B
        int idx = tid + i * 512;
        int row = idx >> 3, ch = idx & 7;
        cp16(so + row * 128 + ((uint32_t)(ch ^ (row & 7)) << 4),
             g_Xh + (size_t)(bm + row) * DIN + k0 + ch * 8);
    }
#pragma unroll
    for (int i = 0; i < 2; i++) {                        // B: 128 rows x 128B
        int idx = tid + i * 512;
        int row = idx >> 3, ch = idx & 7;
        cp16(so + 32768u + row * 128 + ((uint32_t)(ch ^ (row & 7)) << 4),
             g_Wt + (size_t)(bn + row) * DIN + k0 + ch * 8);
    }
}

__global__ __launch_bounds__(512) void gemm_mma(const float* __restrict__ qk) {
    extern __shared__ char sm[];
    __shared__ float sred[256][4];
    __shared__ float ssm[256];
    const uint32_t sb = smem_u32(sm);
    const int tid = threadIdx.x;
    const int wid = tid >> 5, lane = tid & 31;
    const int wm = wid >> 2, wn = wid & 3;               // 4 x 4 warps
    const int h  = blockIdx.x;
    const int bn = h << 7;
    const int bm = blockIdx.y * GBM;

    float acc[4][4][4];
#pragma unroll
    for (int a = 0; a < 4; a++)
#pragma unroll
        for (int b = 0; b < 4; b++)
#pragma unroll
            for (int c = 0; c < 4; c++) acc[a][b][c] = 0.f;

    // ldmatrix per-thread geometry
    const int arow = lane & 15;
    const int asel = lane >> 4;
    const int asw  = arow & 7;
    const int brow = (lane & 7) | (((lane >> 4) & 1) << 3);
    const int bsel = (lane >> 3) & 1;
    const int bsw  = brow & 7;
    uint32_t a_off[4], b_off[2];
#pragma unroll
    for (int mt = 0; mt < 4; mt++) a_off[mt] = (uint32_t)(wm * 64 + mt * 16 + arow) * 128;
#pragma unroll
    for (int bt = 0; bt < 2; bt++) b_off[bt] = 32768u + (uint32_t)(wn * 32 + bt * 16 + brow) * 128;

    // pipeline prologue
    for (int s = 0; s < STAGES - 1; s++) {
        issue_stage(sb, s, s, bm, bn, tid);
        asm volatile("cp.async.commit_group;" ::: "memory");
    }

    for (int kc = 0; kc < KITERS; kc++) {
        asm volatile("cp.async.wait_group 2;" ::: "memory");
        __syncthreads();

        if (kc + STAGES - 1 < KITERS)
            issue_stage(sb, (kc + STAGES - 1) & (STAGES - 1), kc + STAGES - 1, bm, bn, tid);
        asm volatile("cp.async.commit_group;" ::: "memory");

        const uint32_t so = sb + (uint32_t)(kc & (STAGES - 1)) * STAGE_BYTES;
        // B-fragment double buffer: prefetch ks+1 while issuing mma for ks
        uint32_t bf[2][2][4];
#pragma unroll
        for (int bt = 0; bt < 2; bt++)
            ldm4(bf[0][bt], so + b_off[bt] + ((uint32_t)(bsel ^ bsw) << 4));
#pragma unroll
        for (int ks = 0; ks < 4; ks++) {
            uint32_t af[4][4];
#pragma unroll
            for (int mt = 0; mt < 4; mt++)
                ldm4(af[mt], so + a_off[mt] + ((uint32_t)(((ks << 1) | asel) ^ asw) << 4));
            if (ks < 3) {
#pragma unroll
                for (int bt = 0; bt < 2; bt++)
                    ldm4(bf[(ks + 1) & 1][bt],
                         so + b_off[bt] + ((uint32_t)((((ks + 1) << 1) | bsel) ^ bsw) << 4));
            }
            const uint32_t (*bcur)[4] = bf[ks & 1];
#pragma unroll
            for (int mt = 0; mt < 4; mt++) {
                mma16816(acc[mt][0], af[mt], &bcur[0][0]);
                mma16816(acc[mt][1], af[mt], &bcur[0][2]);
                mma16816(acc[mt][2], af[mt], &bcur[1][0]);
                mma16816(acc[mt][3], af[mt], &bcur[1][2]);
            }
        }
    }

    // ------------- fused epilogue -------------
    // c0,c1 = (k,v) at row gq; c2,c3 = (k,v) at row gq+8; d = wn*16+nt*4+qd
    const int gq = lane >> 2, qd = lane & 3;
    float qv[4];
#pragma unroll
    for (int nt = 0; nt < 4; nt++)
        qv[nt] = __ldg(&qk[h * DD + wn * 16 + nt * 4 + qd]);

#pragma unroll
    for (int mt = 0; mt < 4; mt++) {
        const int ml0 = wm * 64 + mt * 16 + gq;
        float s0 = 0.f, s1 = 0.f;
#pragma unroll
        for (int nt = 0; nt < 4; nt++) {
            float k0 = fmaxf(acc[mt][nt][0], 0.f), v0 = fmaxf(acc[mt][nt][1], 0.f);
            float k1 = fmaxf(acc[mt][nt][2], 0.f), v1 = fmaxf(acc[mt][nt][3], 0.f);
            s0 += qv[nt] * k0;
            s1 += qv[nt] * k1;
            acc[mt][nt][1] = v0;                 // keep relu'd v for aggregates
            acc[mt][nt][3] = v1;
        }
        s0 += __shfl_xor_sync(0xFFFFFFFF, s0, 1);
        s0 += __shfl_xor_sync(0xFFFFFFFF, s0, 2);
        s1 += __shfl_xor_sync(0xFFFFFFFF, s1, 1);
        s1 += __shfl_xor_sync(0xFFFFFFFF, s1, 2);
        if (qd == 0) {
            sred[ml0][wn]     = s0;
            sred[ml0 + 8][wn] = s1;
        }
    }
    __syncthreads();
    if (tid < 256) {
        float s = sred[tid][0] + sred[tid][1] + sred[tid][2] + sred[tid][3];
        g_s[(bm + tid) * HH + h] = s;
        ssm[tid] = s;
    }
    __syncthreads();

    // ---- per-chunk aggregates (wm = chunk within the 256-row tile) ----
    float sr[4][2];
#pragma unroll
    for (int mt = 0; mt < 4; mt++) {
        sr[mt][0] = ssm[wm * 64 + mt * 16 + gq];
        sr[mt][1] = ssm[wm * 64 + mt * 16 + gq + 8];
    }
    float lm = -1e30f;
#pragma unroll
    for (int mt = 0; mt < 4; mt++) {
        lm = fmaxf(lm, sr[mt][0]);
        lm = fmaxf(lm, sr[mt][1]);
    }
    lm = fmaxf(lm, __shfl_xor_sync(0xFFFFFFFF, lm, 4));
    lm = fmaxf(lm, __shfl_xor_sync(0xFFFFFFFF, lm, 8));
    lm = fmaxf(lm, __shfl_xor_sync(0xFFFFFFFF, lm, 16));

    float e[4][2];
    float lu = 0.f;
#pragma unroll
    for (int mt = 0; mt < 4; mt++) {
        e[mt][0] = __expf(sr[mt][0] - lm);
        e[mt][1] = __expf(sr[mt][1] - lm);
        lu += e[mt][0] + e[mt][1];
    }
    float wv[4] = {0.f, 0.f, 0.f, 0.f};
#pragma unroll
    for (int nt = 0; nt < 4; nt++)
#pragma unroll
        for (int mt = 0; mt < 4; mt++)
            wv[nt] += e[mt][0] * acc[mt][nt][1] + e[mt][1] * acc[mt][nt][3];
#pragma unroll
    for (int mask = 4; mask <= 16; mask <<= 1) {
        lu += __shfl_xor_sync(0xFFFFFFFF, lu, mask);
#pragma unroll
        for (int nt = 0; nt < 4; nt++)
            wv[nt] += __shfl_xor_sync(0xFFFFFFFF, wv[nt], mask);
    }
    const int crow = (bm >> 6) + wm;                       // global chunk row
    const int cidx = ((crow >> 6) * HH + h) * CC + (crow & 63);
    if (gq == 0) {
#pragma unroll
        for (int nt = 0; nt < 4; nt++)
            g_cw[cidx * DD + wn * 16 + nt * 4 + qd] = wv[nt];
        if (qd == 0 && wn == 0) { g_cm[cidx] = lm; g_cu[cidx] = lu; }
    }

    // ---- stage v (fp16) into now-idle pipeline smem, then coalesced write ----
    // layout: [256 rows][72 halfs] (144B stride: 16B-aligned, bank-shift 4/row)
    __half* svh = (__half*)sm;
#pragma unroll
    for (int mt = 0; mt < 4; mt++) {
        const int ml0 = wm * 64 + mt * 16 + gq;
#pragma unroll
        for (int nt = 0; nt < 4; nt++) {
            const int dl = wn * 16 + nt * 4 + qd;
            svh[ml0 * 72 + dl]       = __float2half_rn(acc[mt][nt][1]);
            svh[(ml0 + 8) * 72 + dl] = __float2half_rn(acc[mt][nt][3]);
        }
    }
    __syncthreads();
    const uint4* src4 = (const uint4*)sm;
#pragma unroll
    for (int i = 0; i < 4; i++) {
        int idx = tid + i * 512;                 // < 2048
        int row = idx >> 3, part = idx & 7;
        *((uint4*)(g_vh + (size_t)(bm + row) * (HH*DD) + h * DD + part * 8)) =
            src4[row * 9 + part];
    }
}

// ---------------------------------------------------------------------------
// Scan phase B: exclusive scan over chunk aggregates, smem-staged.
// grid = B*H, 64 threads (measured faster than 256-thread variant).
// ---------------------------------------------------------------------------
__global__ __launch_bounds__(64) void scanB() {
    __shared__ float scm[CC], scu[CC], scw[CC * DD];
    const int bh = blockIdx.x;
    const int d  = threadIdx.x;

    for (int c = 0; c < CC; c++)
        scw[c * DD + d] = g_cw[(bh * CC + c) * DD + d];
    scm[d] = g_cm[bh * CC + d];
    scu[d] = g_cu[bh * CC + d];
    __syncthreads();

    float mC = -1e30f, uC = 0.f, wC = 0.f;
    for (int c = 0; c < CC; c++) {
        const int idx = bh * CC + c;
        const float ma = scm[c];
        const float ua = scu[c];
        const float wa = scw[c * DD + d];
        g_cw[idx * DD + d] = wC;                    // exclusive prefix out
        if (d == 0) { g_cm[idx] = mC; g_cu[idx] = uC; }
        if (ma > mC) {
            const float a = __expf(mC - ma);
            uC = uC * a + ua;
            wC = wC * a + wa;
            mC = ma;
        } else {
            const float eb = __expf(ma - mC);
            uC += ua * eb;
            wC += wa * eb;
        }
    }
}

// ---------------------------------------------------------------------------
// Scan phase C fused with head-reduction: out[b,t,d] = sum_h w/u.
// grid = (B*C, 2) blocks, 128 threads (4 h-groups x 32 d). The block's full
// v-tile (64t x 16h x 32d fp16 = 64KB) is staged into smem via cp.async up
// front, so the serial scan reads only smem. Slab reduction across h-groups.
// ---------------------------------------------------------------------------
__global__ __launch_bounds__(128) void scanCR(float* __restrict__ out) {
    extern __shared__ float dyn[];
    // layout: vtile 64KB (fp16) | slab 4*64*32 floats (32KB) | s_sm 1024 floats (4KB)
    __half* vtile = (__half*)dyn;
    float*  slab  = dyn + (LL * HH * 32 * 2) / 4;       // +16384 floats
    float*  s_sm  = slab + 4 * LL * 32;
    const int b     = blockIdx.x / CC;
    const int c     = blockIdx.x % CC;
    const int dhalf = blockIdx.y;                        // 0 or 1
    const int tid   = threadIdx.x;
    const int hs    = tid >> 5;                          // 0..3
    const int dl    = tid & 31;                          // local d
    const int t0    = c * LL;

    // stage v tile: 64 rows x 16 heads x 32 halfs (64B segments)
    const uint32_t vbase = smem_u32(vtile);
#pragma unroll
    for (int i = 0; i < 32; i++) {
        int idx = tid + i * 128;                         // < 4096
        int tt = idx >> 6, rem = idx & 63;
        int h = rem >> 2, seg = rem & 3;
        cp16(vbase + (uint32_t)(((tt * HH + h) * 32 + seg * 8) * 2),
             g_vh + (size_t)(b * TT + t0 + tt) * (HH*DD) + h * DD + dhalf * 32 + seg * 8);
    }
    asm volatile("cp.async.commit_group;" ::: "memory");

    // stage s block: contiguous 1024 floats
    for (int i = tid; i < 256; i += 128)
        ((float4*)s_sm)[i] = ((const float4*)(g_s + (size_t)(b * TT + t0) * HH))[i];

    float m[4], u[4], w[4];
#pragma unroll
    for (int hi = 0; hi < 4; hi++) {
        const int h   = hs * 4 + hi;
        const int idx = (b * HH + h) * CC + c;
        m[hi] = g_cm[idx];
        u[hi] = g_cu[idx];
        w[hi] = g_cw[idx * DD + dhalf * 32 + dl];
    }
    asm volatile("cp.async.wait_group 0;" ::: "memory");
    __syncthreads();

    float* myslab = slab + hs * LL * 32;
#pragma unroll 4
    for (int tt = 0; tt < LL; tt++) {
        float sum = 0.f;
#pragma unroll
        for (int hi = 0; hi < 4; hi++) {
            const int h = hs * 4 + hi;
            const float s = s_sm[tt * HH + h];
            const float v = __half2float(vtile[(tt * HH + h) * 32 + dl]);
            if (s > m[hi]) {                             // warp-uniform branch
                const float a = __expf(m[hi] - s);
                u[hi] = u[hi] * a + 1.f;
                w[hi] = w[hi] * a + v;
                m[hi] = s;
            } else {
                const float ex = __expf(s - m[hi]);
                u[hi] += ex;
                w[hi] += ex * v;
            }
            sum += __fdividef(w[hi], u[hi]);
        }
        myslab[tt * 32 + dl] = sum;
    }
    __syncthreads();
    for (int i = tid; i < LL * 32; i += 128) {
        const int tt = i >> 5, dd = i & 31;
        out[((size_t)b * TT + t0 + tt) * DD + dhalf * 32 + dd] =
            slab[i] + slab[LL*32 + i] + slab[2*LL*32 + i] + slab[3*LL*32 + i];
    }
}

extern "C" void kernel_launch(void* const* d_in, const int* in_sizes, int n_in,
                              void* d_out, int out_size) {
    const float* X = (const float*)d_in[0];   // [B,T,DIN]
    const float* W = (const float*)d_in[1];   // [DIN, 2048]
    const float* q = (const float*)d_in[2];   // [H,D]
    float* out = (float*)d_out;               // [B,T,D]

    const int gemm_smem = STAGES * (int)STAGE_BYTES;                 // 196608
    const int scan_smem = LL * HH * 32 * 2                           // v tile 64KB
                        + 4 * LL * 32 * (int)sizeof(float)           // slab  32KB
                        + LL * HH * (int)sizeof(float);              // s     4KB
    cudaFuncSetAttribute(gemm_mma, cudaFuncAttributeMaxDynamicSharedMemorySize,
                         gemm_smem);
    cudaFuncSetAttribute(scanCR, cudaFuncAttributeMaxDynamicSharedMemorySize,
                         scan_smem);

    convXW<<<8192 + 2048, 256>>>(X, W);
    gemm_mma<<<dim3(HH, MM / GBM), 512, gemm_smem>>>(q);
    scanB<<<BB * HH, 64>>>();
    scanCR<<<dim3(BB * CC, 2), 128, scan_smem>>>(out);
}

// round 11
// speedup vs baseline: 7.1564x; 1.0817x over previous
#include <cuda_runtime.h>
#include <cuda_fp16.h>
#include <math.h>
#include <stdint.h>

// Problem constants
#define BB   4
#define TT   4096
#define DIN  1024
#define HH   16
#define DD   64
#define MM   (BB*TT)        // 16384
#define NN   (HH*DD*2)      // 2048
#define CC   64             // scan chunks per (b,h)
#define LL   (TT/CC)        // 64

// GEMM tiling: 256x128x64, 512 threads (16 warps, 4x4, warp tile 64x32)
#define GBM 256
#define GBN 128
#define GBK 64
#define STAGES 4
#define KITERS (DIN/GBK)    // 16
#define STAGE_BYTES 49152u  // 32KB A + 16KB B

// ---------------------------------------------------------------------------
// Scratch (device globals; no allocation allowed)
// ---------------------------------------------------------------------------
__device__ __half g_Xh[(size_t)MM * DIN];      // 32 MiB
__device__ __half g_Wt[(size_t)NN * DIN];      // 4 MiB  (transposed W: [n][k])
__device__ __half g_vh[(size_t)MM * (HH*DD)];  // 32 MiB packed relu(v) fp16
__device__ float  g_s[MM * HH];                // 1 MiB
__device__ float  g_cm[BB*HH*CC];
__device__ float  g_cu[BB*HH*CC];
__device__ float  g_cw[BB*HH*CC*DD];

// ---------------------------------------------------------------------------
// asm helpers
// ---------------------------------------------------------------------------
__device__ __forceinline__ uint32_t smem_u32(const void* p) {
    uint32_t a;
    asm("{ .reg .u64 t; cvta.to.shared.u64 t, %1; cvt.u32.u64 %0, t; }" : "=r"(a) : "l"(p));
    return a;
}
__device__ __forceinline__ void cp16(uint32_t dst, const void* src) {
    asm volatile("cp.async.cg.shared.global [%0], [%1], 16;" :: "r"(dst), "l"(src));
}
__device__ __forceinline__ void ldm4(uint32_t* r, uint32_t addr) {
    asm volatile("ldmatrix.sync.aligned.m8n8.x4.shared.b16 {%0,%1,%2,%3}, [%4];"
                 : "=r"(r[0]), "=r"(r[1]), "=r"(r[2]), "=r"(r[3]) : "r"(addr));
}
__device__ __forceinline__ void mma16816(float* c, const uint32_t* a, const uint32_t* b) {
    asm volatile("mma.sync.aligned.m16n8k16.row.col.f32.f16.f16.f32 "
                 "{%0,%1,%2,%3}, {%4,%5,%6,%7}, {%8,%9}, {%0,%1,%2,%3};"
                 : "+f"(c[0]), "+f"(c[1]), "+f"(c[2]), "+f"(c[3])
                 : "r"(a[0]), "r"(a[1]), "r"(a[2]), "r"(a[3]), "r"(b[0]), "r"(b[1]));
}
__device__ __forceinline__ float rcp_approx(float x) {
    float r;
    asm("rcp.approx.f32 %0, %1;" : "=f"(r) : "f"(x));
    return r;
}

// ---------------------------------------------------------------------------
// Fused prep: blocks [0, 8192) convert X fp32 -> fp16 (8 floats / thread);
// blocks [8192, 10240) transpose+convert W [K][N] fp32 -> g_Wt fp16 [N][K].
// ---------------------------------------------------------------------------
__global__ __launch_bounds__(256) void convXW(const float* __restrict__ X,
                                              const float* __restrict__ W) {
    const int tid = threadIdx.x;
    if (blockIdx.x < 8192) {
        size_t i = (size_t)blockIdx.x * 256 + tid;       // < 2M
        const float4* src = (const float4*)X + i * 2;
        float4 x0 = src[0], x1 = src[1];
        __half2 h0 = __floats2half2_rn(x0.x, x0.y);
        __half2 h1 = __floats2half2_rn(x0.z, x0.w);
        __half2 h2 = __floats2half2_rn(x1.x, x1.y);
        __half2 h3 = __floats2half2_rn(x1.z, x1.w);
        uint4 o;
        o.x = *(uint32_t*)&h0; o.y = *(uint32_t*)&h1;
        o.z = *(uint32_t*)&h2; o.w = *(uint32_t*)&h3;
        ((uint4*)g_Xh)[i] = o;
    } else {
        __shared__ float tile[32][33];
        const int bw = blockIdx.x - 8192;                // < 2048
        const int n0 = (bw & 63) * 32, k0 = (bw >> 6) * 32;
        const int tx = tid & 31, ty = tid >> 5;          // 32 x 8
        for (int r = ty; r < 32; r += 8)
            tile[r][tx] = W[(size_t)(k0 + r) * NN + n0 + tx];
        __syncthreads();
        for (int r = ty; r < 32; r += 8)
            g_Wt[(size_t)(n0 + r) * DIN + k0 + tx] = __float2half(tile[tx][r]);
    }
}

// ---------------------------------------------------------------------------
// GEMM via mma.sync: kv = relu(X @ W); fused: de-interleave v (fp16, smem-
// staged coalesced store), s = q.relu(k), and per-chunk scan aggregates.
// CTA 256x128x64, 512 threads, 4-stage cp.async, B-fragment double buffer.
// blockIdx.x = head h, blockIdx.y = M-tile (256 rows = 4 scan chunks).
// ---------------------------------------------------------------------------
__device__ __forceinline__ void issue_stage(uint32_t sb, int stage, int kc,
                                            int bm, int bn, int tid) {
    const uint32_t so = sb + (uint32_t)stage * STAGE_BYTES;
    const int k0 = kc * GBK;
#pragma unroll
    for (int i = 0; i < 4; i++) {                        // A: 256 rows x 128B
        int idx = tid + i * 512;
        int row = idx >> 3, ch = idx & 7;
        cp16(so + row * 128 + ((uint32_t)(ch ^ (row & 7)) << 4),
             g_Xh + (size_t)(bm + row) * DIN + k0 + ch * 8);
    }
#pragma unroll
    for (int i = 0; i < 2; i++) {                        // B: 128 rows x 128B
        int idx = tid + i * 512;
        int row = idx >> 3, ch = idx & 7;
        cp16(so + 32768u + row * 128 + ((uint32_t)(ch ^ (row & 7)) << 4),
             g_Wt + (size_t)(bn + row) * DIN + k0 + ch * 8);
    }
}

__global__ __launch_bounds__(512) void gemm_mma(const float* __restrict__ qk) {
    extern __shared__ char sm[];
    __shared__ float sred[256][4];
    __shared__ float ssm[256];
    const uint32_t sb = smem_u32(sm);
    const int tid = threadIdx.x;
    const int wid = tid >> 5, lane = tid & 31;
    const int wm = wid >> 2, wn = wid & 3;               // 4 x 4 warps
    const int h  = blockIdx.x;
    const int bn = h << 7;
    const int bm = blockIdx.y * GBM;

    float acc[4][4][4];
#pragma unroll
    for (int a = 0; a < 4; a++)
#pragma unroll
        for (int b = 0; b < 4; b++)
#pragma unroll
            for (int c = 0; c < 4; c++) acc[a][b][c] = 0.f;

    // ldmatrix per-thread geometry
    const int arow = lane & 15;
    const int asel = lane >> 4;
    const int asw  = arow & 7;
    const int brow = (lane & 7) | (((lane >> 4) & 1) << 3);
    const int bsel = (lane >> 3) & 1;
    const int bsw  = brow & 7;
    uint32_t a_off[4], b_off[2];
#pragma unroll
    for (int mt = 0; mt < 4; mt++) a_off[mt] = (uint32_t)(wm * 64 + mt * 16 + arow) * 128;
#pragma unroll
    for (int bt = 0; bt < 2; bt++) b_off[bt] = 32768u + (uint32_t)(wn * 32 + bt * 16 + brow) * 128;

    // pipeline prologue
    for (int s = 0; s < STAGES - 1; s++) {
        issue_stage(sb, s, s, bm, bn, tid);
        asm volatile("cp.async.commit_group;" ::: "memory");
    }

    for (int kc = 0; kc < KITERS; kc++) {
        asm volatile("cp.async.wait_group 2;" ::: "memory");
        __syncthreads();

        if (kc + STAGES - 1 < KITERS)
            issue_stage(sb, (kc + STAGES - 1) & (STAGES - 1), kc + STAGES - 1, bm, bn, tid);
        asm volatile("cp.async.commit_group;" ::: "memory");

        const uint32_t so = sb + (uint32_t)(kc & (STAGES - 1)) * STAGE_BYTES;
        // B-fragment double buffer: prefetch ks+1 while issuing mma for ks
        uint32_t bf[2][2][4];
#pragma unroll
        for (int bt = 0; bt < 2; bt++)
            ldm4(bf[0][bt], so + b_off[bt] + ((uint32_t)(bsel ^ bsw) << 4));
#pragma unroll
        for (int ks = 0; ks < 4; ks++) {
            uint32_t af[4][4];
#pragma unroll
            for (int mt = 0; mt < 4; mt++)
                ldm4(af[mt], so + a_off[mt] + ((uint32_t)(((ks << 1) | asel) ^ asw) << 4));
            if (ks < 3) {
#pragma unroll
                for (int bt = 0; bt < 2; bt++)
                    ldm4(bf[(ks + 1) & 1][bt],
                         so + b_off[bt] + ((uint32_t)((((ks + 1) << 1) | bsel) ^ bsw) << 4));
            }
            const uint32_t (*bcur)[4] = bf[ks & 1];
#pragma unroll
            for (int mt = 0; mt < 4; mt++) {
                mma16816(acc[mt][0], af[mt], &bcur[0][0]);
                mma16816(acc[mt][1], af[mt], &bcur[0][2]);
                mma16816(acc[mt][2], af[mt], &bcur[1][0]);
                mma16816(acc[mt][3], af[mt], &bcur[1][2]);
            }
        }
    }

    // ------------- fused epilogue -------------
    // c0,c1 = (k,v) at row gq; c2,c3 = (k,v) at row gq+8; d = wn*16+nt*4+qd
    const int gq = lane >> 2, qd = lane & 3;
    float qv[4];
#pragma unroll
    for (int nt = 0; nt < 4; nt++)
        qv[nt] = __ldg(&qk[h * DD + wn * 16 + nt * 4 + qd]);

#pragma unroll
    for (int mt = 0; mt < 4; mt++) {
        const int ml0 = wm * 64 + mt * 16 + gq;
        float s0 = 0.f, s1 = 0.f;
#pragma unroll
        for (int nt = 0; nt < 4; nt++) {
            float k0 = fmaxf(acc[mt][nt][0], 0.f), v0 = fmaxf(acc[mt][nt][1], 0.f);
            float k1 = fmaxf(acc[mt][nt][2], 0.f), v1 = fmaxf(acc[mt][nt][3], 0.f);
            s0 += qv[nt] * k0;
            s1 += qv[nt] * k1;
            acc[mt][nt][1] = v0;                 // keep relu'd v for aggregates
            acc[mt][nt][3] = v1;
        }
        s0 += __shfl_xor_sync(0xFFFFFFFF, s0, 1);
        s0 += __shfl_xor_sync(0xFFFFFFFF, s0, 2);
        s1 += __shfl_xor_sync(0xFFFFFFFF, s1, 1);
        s1 += __shfl_xor_sync(0xFFFFFFFF, s1, 2);
        if (qd == 0) {
            sred[ml0][wn]     = s0;
            sred[ml0 + 8][wn] = s1;
        }
    }
    __syncthreads();
    if (tid < 256) {
        float s = sred[tid][0] + sred[tid][1] + sred[tid][2] + sred[tid][3];
        g_s[(bm + tid) * HH + h] = s;
        ssm[tid] = s;
    }
    __syncthreads();

    // ---- per-chunk aggregates (wm = chunk within the 256-row tile) ----
    float sr[4][2];
#pragma unroll
    for (int mt = 0; mt < 4; mt++) {
        sr[mt][0] = ssm[wm * 64 + mt * 16 + gq];
        sr[mt][1] = ssm[wm * 64 + mt * 16 + gq + 8];
    }
    float lm = -1e30f;
#pragma unroll
    for (int mt = 0; mt < 4; mt++) {
        lm = fmaxf(lm, sr[mt][0]);
        lm = fmaxf(lm, sr[mt][1]);
    }
    lm = fmaxf(lm, __shfl_xor_sync(0xFFFFFFFF, lm, 4));
    lm = fmaxf(lm, __shfl_xor_sync(0xFFFFFFFF, lm, 8));
    lm = fmaxf(lm, __shfl_xor_sync(0xFFFFFFFF, lm, 16));

    float e[4][2];
    float lu = 0.f;
#pragma unroll
    for (int mt = 0; mt < 4; mt++) {
        e[mt][0] = __expf(sr[mt][0] - lm);
        e[mt][1] = __expf(sr[mt][1] - lm);
        lu += e[mt][0] + e[mt][1];
    }
    float wv[4] = {0.f, 0.f, 0.f, 0.f};
#pragma unroll
    for (int nt = 0; nt < 4; nt++)
#pragma unroll
        for (int mt = 0; mt < 4; mt++)
            wv[nt] += e[mt][0] * acc[mt][nt][1] + e[mt][1] * acc[mt][nt][3];
#pragma unroll
    for (int mask = 4; mask <= 16; mask <<= 1) {
        lu += __shfl_xor_sync(0xFFFFFFFF, lu, mask);
#pragma unroll
        for (int nt = 0; nt < 4; nt++)
            wv[nt] += __shfl_xor_sync(0xFFFFFFFF, wv[nt], mask);
    }
    const int crow = (bm >> 6) + wm;                       // global chunk row
    const int cidx = ((crow >> 6) * HH + h) * CC + (crow & 63);
    if (gq == 0) {
#pragma unroll
        for (int nt = 0; nt < 4; nt++)
            g_cw[cidx * DD + wn * 16 + nt * 4 + qd] = wv[nt];
        if (qd == 0 && wn == 0) { g_cm[cidx] = lm; g_cu[cidx] = lu; }
    }

    // ---- stage v (fp16) into now-idle pipeline smem, then coalesced write ----
    // layout: [256 rows][72 halfs] (144B stride: 16B-aligned, bank-shift 4/row)
    __half* svh = (__half*)sm;
#pragma unroll
    for (int mt = 0; mt < 4; mt++) {
        const int ml0 = wm * 64 + mt * 16 + gq;
#pragma unroll
        for (int nt = 0; nt < 4; nt++) {
            const int dl = wn * 16 + nt * 4 + qd;
            svh[ml0 * 72 + dl]       = __float2half_rn(acc[mt][nt][1]);
            svh[(ml0 + 8) * 72 + dl] = __float2half_rn(acc[mt][nt][3]);
        }
    }
    __syncthreads();
    const uint4* src4 = (const uint4*)sm;
#pragma unroll
    for (int i = 0; i < 4; i++) {
        int idx = tid + i * 512;                 // < 2048
        int row = idx >> 3, part = idx & 7;
        *((uint4*)(g_vh + (size_t)(bm + row) * (HH*DD) + h * DD + part * 8)) =
            src4[row * 9 + part];
    }
}

// ---------------------------------------------------------------------------
// Scan phase B: exclusive scan over chunk aggregates, smem-staged.
// grid = B*H, 64 threads (measured faster than 256-thread variant).
// ---------------------------------------------------------------------------
__global__ __launch_bounds__(64) void scanB() {
    __shared__ float scm[CC], scu[CC], scw[CC * DD];
    const int bh = blockIdx.x;
    const int d  = threadIdx.x;

    for (int c = 0; c < CC; c++)
        scw[c * DD + d] = g_cw[(bh * CC + c) * DD + d];
    scm[d] = g_cm[bh * CC + d];
    scu[d] = g_cu[bh * CC + d];
    __syncthreads();

    float mC = -1e30f, uC = 0.f, wC = 0.f;
    for (int c = 0; c < CC; c++) {
        const int idx = bh * CC + c;
        const float ma = scm[c];
        const float ua = scu[c];
        const float wa = scw[c * DD + d];
        g_cw[idx * DD + d] = wC;                    // exclusive prefix out
        if (d == 0) { g_cm[idx] = mC; g_cu[idx] = uC; }
        if (ma > mC) {
            const float a = __expf(mC - ma);
            uC = uC * a + ua;
            wC = wC * a + wa;
            mC = ma;
        } else {
            const float eb = __expf(ma - mC);
            uC += ua * eb;
            wC += wa * eb;
        }
    }
}

// ---------------------------------------------------------------------------
// Scan phase C fused with head-reduction: out[b,t,d] = sum_h w/u.
// grid = (B*C, 2), 128 threads (4 h-group warps x 32 d). v streamed from
// gmem in 8-tt waves via double-buffered cp.async (2 x 8KB smem) instead of
// a resident 64KB tile -> 4 blocks/SM. One combined rcp per tt (p=u0u1u2u3)
// instead of 4 divides -> MUFU per tt 8 -> 5.
// smem: vbuf 16KB | slab 32KB | s 4KB = 52KB.
// ---------------------------------------------------------------------------
#define SCW  8                                  // tt per wave
#define NWAVE (LL/SCW)                          // 8
#define VWAVE_HALFS (SCW * HH * 32)             // 4096 halfs = 8KB

__global__ __launch_bounds__(128) void scanCR(float* __restrict__ out) {
    extern __shared__ float dyn[];
    __half* vbuf = (__half*)dyn;                         // 2 waves x 8KB
    float*  slab = dyn + (2 * VWAVE_HALFS) / 2;          // + 8192 floats offset /2 in floats
    float*  s_sm = slab + 4 * LL * 32;
    const int b     = blockIdx.x / CC;
    const int c     = blockIdx.x % CC;
    const int dhalf = blockIdx.y;                        // 0 or 1
    const int tid   = threadIdx.x;
    const int hs    = tid >> 5;                          // 0..3 (warp = h-group)
    const int dl    = tid & 31;                          // local d
    const int t0    = c * LL;

    const uint32_t vbase = smem_u32(vbuf);
    const __half* vsrc = g_vh + (size_t)(b * TT + t0) * (HH*DD) + dhalf * 32;

    // issue one 8-tt wave into buffer (wv & 1): 512 cp16, 4 per thread
    auto issue_wave = [&](int wv) {
        const uint32_t bofs = (uint32_t)((wv & 1) * VWAVE_HALFS * 2);
#pragma unroll
        for (int i = 0; i < 4; i++) {
            int idx = tid + i * 128;                     // < 512
            int ttl = idx >> 6, rem = idx & 63;
            int h = rem >> 2, seg = rem & 3;
            cp16(vbase + bofs + (uint32_t)(((ttl * HH + h) * 32 + seg * 8) * 2),
                 vsrc + (size_t)(wv * SCW + ttl) * (HH*DD) + h * DD + seg * 8);
        }
        asm volatile("cp.async.commit_group;" ::: "memory");
    };

    issue_wave(0);
    issue_wave(1);

    // stage s block: contiguous 1024 floats
    for (int i = tid; i < 256; i += 128)
        ((float4*)s_sm)[i] = ((const float4*)(g_s + (size_t)(b * TT + t0) * HH))[i];

    float m[4], u[4], w[4];
#pragma unroll
    for (int hi = 0; hi < 4; hi++) {
        const int h   = hs * 4 + hi;
        const int idx = (b * HH + h) * CC + c;
        m[hi] = g_cm[idx];
        u[hi] = g_cu[idx];
        w[hi] = g_cw[idx * DD + dhalf * 32 + dl];
    }

    float* myslab = slab + hs * LL * 32;
    for (int wv = 0; wv < NWAVE; wv++) {
        if (wv < NWAVE - 2)
            asm volatile("cp.async.wait_group 1;" ::: "memory");
        else
            asm volatile("cp.async.wait_group 0;" ::: "memory");
        __syncthreads();

        const __half* vb = vbuf + (wv & 1) * VWAVE_HALFS;
#pragma unroll
        for (int ttl = 0; ttl < SCW; ttl++) {
            const int tt = wv * SCW + ttl;
#pragma unroll
            for (int hi = 0; hi < 4; hi++) {
                const int h = hs * 4 + hi;
                const float s = s_sm[tt * HH + h];
                const float v = __half2float(vb[(ttl * HH + h) * 32 + dl]);
                if (s > m[hi]) {                         // warp-uniform branch
                    const float a = __expf(m[hi] - s);
                    u[hi] = u[hi] * a + 1.f;
                    w[hi] = w[hi] * a + v;
                    m[hi] = s;
                } else {
                    const float ex = __expf(s - m[hi]);
                    u[hi] += ex;
                    w[hi] += ex * v;
                }
            }
            // one rcp for all four heads: 1/ui = prod(others) * rcp(prod(all))
            const float p01 = u[0] * u[1];
            const float p23 = u[2] * u[3];
            const float rp  = rcp_approx(p01 * p23);
            float sum = (w[0] * u[1] + w[1] * u[0]) * (rp * p23)
                      + (w[2] * u[3] + w[3] * u[2]) * (rp * p01);
            myslab[tt * 32 + dl] = sum;
        }
        __syncthreads();                                  // done reading buffer
        if (wv + 2 < NWAVE) issue_wave(wv + 2);
    }

    for (int i = tid; i < LL * 32; i += 128) {
        const int tt = i >> 5, dd = i & 31;
        out[((size_t)b * TT + t0 + tt) * DD + dhalf * 32 + dd] =
            slab[i] + slab[LL*32 + i] + slab[2*LL*32 + i] + slab[3*LL*32 + i];
    }
}

extern "C" void kernel_launch(void* const* d_in, const int* in_sizes, int n_in,
                              void* d_out, int out_size) {
    const float* X = (const float*)d_in[0];   // [B,T,DIN]
    const float* W = (const float*)d_in[1];   // [DIN, 2048]
    const float* q = (const float*)d_in[2];   // [H,D]
    float* out = (float*)d_out;               // [B,T,D]

    const int gemm_smem = STAGES * (int)STAGE_BYTES;                 // 196608
    const int scan_smem = 2 * VWAVE_HALFS * 2                        // v ring 16KB
                        + 4 * LL * 32 * (int)sizeof(float)           // slab  32KB
                        + LL * HH * (int)sizeof(float);              // s     4KB
    cudaFuncSetAttribute(gemm_mma, cudaFuncAttributeMaxDynamicSharedMemorySize,
                         gemm_smem);
    cudaFuncSetAttribute(scanCR, cudaFuncAttributeMaxDynamicSharedMemorySize,
                         scan_smem);

    convXW<<<8192 + 2048, 256>>>(X, W);
    gemm_mma<<<dim3(HH, MM / GBM), 512, gemm_smem>>>(q);
    scanB<<<BB * HH, 64>>>();
    scanCR<<<dim3(BB * CC, 2), 128, scan_smem>>>(out);
}